// round 10
// baseline (speedup 1.0000x reference)
#include <cuda_runtime.h>
#include <cuda_bf16.h>
#include <math.h>
#include <cstdint>

#define NB 256
#define NR 36
#define NL 40
#define ND 1024
#define MT (NB * NR)   /* 9216  */
#define NT (NB * NL)   /* 10240 */
#define EPSF 1e-8f
#define LAMS 9.0f

#define MROWS 9472     /* 9216 img rows + 256 pool_img */
#define NROWS 10496    /* 10240 cap rows + 256 pool_txt */

// ---- scratch (device globals; no allocation allowed) ----
__device__ float g_S[(size_t)MT * NT];           // S^T[n][m], leaky-relu'd (378MB)
__device__ __nv_bfloat16 g_Ah[(size_t)MROWS * ND];  // bf16 img_emb ++ pool_img
__device__ __nv_bfloat16 g_Bh[(size_t)NROWS * ND];  // bf16 cap_emb ++ pool_txt
__device__ float g_P[NB * NB * NR];
__device__ float g_Q[NB * NB * NL];
__device__ float g_G[NB * NR * NR];
__device__ float g_H[NB * NL * NL];
__device__ float g_base[NB * NB];
__device__ float g_w1i[NB];
__device__ float g_w1t[NB];

__device__ __forceinline__ float4 ldg4(const float* p) {
    return *reinterpret_cast<const float4*>(p);
}
__device__ __forceinline__ uint32_t pack_bf2(float x, float y) {
    __nv_bfloat162 h = __float22bfloat162_rn(make_float2(x, y));
    return *reinterpret_cast<uint32_t*>(&h);
}
__device__ __forceinline__ void mma_bf16(float* c, const uint32_t* a, const uint32_t* b) {
    asm volatile(
        "mma.sync.aligned.m16n8k16.row.col.f32.bf16.bf16.f32 "
        "{%0,%1,%2,%3}, {%4,%5,%6,%7}, {%8,%9}, {%0,%1,%2,%3};"
        : "+f"(c[0]), "+f"(c[1]), "+f"(c[2]), "+f"(c[3])
        : "r"(a[0]), "r"(a[1]), "r"(a[2]), "r"(a[3]), "r"(b[0]), "r"(b[1]));
}
__device__ __forceinline__ void cpa16(uint32_t saddr, const void* gaddr) {
    asm volatile("cp.async.ca.shared.global [%0], [%1], 16;"
                 :: "r"(saddr), "l"(gaddr) : "memory");
}
__device__ __forceinline__ void ldsm_x4(uint32_t& r0, uint32_t& r1, uint32_t& r2,
                                        uint32_t& r3, uint32_t addr) {
    asm volatile("ldmatrix.sync.aligned.m8n8.x4.shared.b16 {%0,%1,%2,%3}, [%4];"
                 : "=r"(r0), "=r"(r1), "=r"(r2), "=r"(r3) : "r"(addr));
}

// ============================ bf16 conversion (augmented operands) ============================
__global__ void cvt_kernel(const float* __restrict__ img, const float* __restrict__ pimg,
                           const float* __restrict__ cap, const float* __restrict__ ptxt) {
    size_t g8 = (size_t)blockIdx.x * 256 + threadIdx.x;
    const size_t A8 = (size_t)MROWS * (ND / 8);
    const float* src;
    uint32_t* dst;
    if (g8 < A8) {
        size_t off = g8 * 8;
        size_t row = off >> 10, col = off & 1023;
        src = (row < 9216) ? (img + row * ND + col) : (pimg + (row - 9216) * ND + col);
        dst = reinterpret_cast<uint32_t*>(g_Ah) + g8 * 4;
    } else {
        size_t h8 = g8 - A8;
        size_t off = h8 * 8;
        size_t row = off >> 10, col = off & 1023;
        src = (row < 10240) ? (cap + row * ND + col) : (ptxt + (row - 10240) * ND + col);
        dst = reinterpret_cast<uint32_t*>(g_Bh) + h8 * 4;
    }
    float4 x = ldg4(src), y = ldg4(src + 4);
    *reinterpret_cast<uint4*>(dst) =
        make_uint4(pack_bf2(x.x, x.y), pack_bf2(x.z, x.w),
                   pack_bf2(y.x, y.y), pack_bf2(y.z, y.w));
}

// ============================ precompute kernels ============================
__global__ void norm_kernel(const float* __restrict__ pi, const float* __restrict__ pt) {
    int w = blockIdx.x * 8 + (threadIdx.x >> 5);
    int lane = threadIdx.x & 31;
    const float* src = (w < NB) ? (pi + (size_t)w * ND) : (pt + (size_t)(w - NB) * ND);
    float s = 0.f;
    for (int j = lane; j < ND; j += 32) { float v = src[j]; s = fmaf(v, v, s); }
#pragma unroll
    for (int o = 16; o; o >>= 1) s += __shfl_down_sync(0xffffffffu, s, o);
    if (lane == 0) {
        float r = sqrtf(s);
        if (w < NB) g_w1i[w] = r; else g_w1t[w - NB] = r;
    }
}

__global__ void sgemm_tn(const float* __restrict__ A, const float* __restrict__ Bm,
                         int M, int N, int K) {
    float* C = g_base;
    __shared__ float As[16 * 64];
    __shared__ float Bs[16 * 64];
    int tid = threadIdx.x;
    int tx = tid & 15, ty = tid >> 4;
    int m0 = blockIdx.y * 64, n0 = blockIdx.x * 64;
    int row = tid >> 2, q = tid & 3;
    float acc[4][4] = {};
    for (int k0 = 0; k0 < K; k0 += 16) {
        float4 a = ldg4(A + (size_t)(m0 + row) * K + k0 + q * 4);
        float4 bb = ldg4(Bm + (size_t)(n0 + row) * K + k0 + q * 4);
        As[(q * 4 + 0) * 64 + row] = a.x;  As[(q * 4 + 1) * 64 + row] = a.y;
        As[(q * 4 + 2) * 64 + row] = a.z;  As[(q * 4 + 3) * 64 + row] = a.w;
        Bs[(q * 4 + 0) * 64 + row] = bb.x; Bs[(q * 4 + 1) * 64 + row] = bb.y;
        Bs[(q * 4 + 2) * 64 + row] = bb.z; Bs[(q * 4 + 3) * 64 + row] = bb.w;
        __syncthreads();
#pragma unroll
        for (int k = 0; k < 16; k++) {
            float4 av = *(const float4*)(As + k * 64 + ty * 4);
            float4 bv = *(const float4*)(Bs + k * 64 + tx * 4);
            float aa[4] = {av.x, av.y, av.z, av.w};
            float bw[4] = {bv.x, bv.y, bv.z, bv.w};
#pragma unroll
            for (int ii = 0; ii < 4; ii++)
#pragma unroll
                for (int jj = 0; jj < 4; jj++)
                    acc[ii][jj] = fmaf(aa[ii], bw[jj], acc[ii][jj]);
        }
        __syncthreads();
    }
#pragma unroll
    for (int ii = 0; ii < 4; ii++)
#pragma unroll
        for (int jj = 0; jj < 4; jj++)
            C[(size_t)(m0 + ty * 4 + ii) * N + n0 + tx * 4 + jj] = acc[ii][jj];
}

// per-row Gram, 4x4 register-blocked, symmetric
__global__ void gram_kernel(const float* __restrict__ emb, int ROWS, int which) {
    extern __shared__ float Es[];
    float* out = which ? g_H : g_G;
    int b = blockIdx.x, tid = threadIdx.x;
    int wid = tid >> 5, lane = tid & 31;
    int n = ROWS * ND;
    int np = ROWS * ROWS;
    for (int idx = tid; idx < n; idx += 256) Es[idx] = emb[(size_t)b * n + idx];
    __syncthreads();
    int nt4 = ROWS / 4;
    int count = nt4 * (nt4 + 1) / 2;
    for (int p = wid; p < count; p += 8) {
        int pl = p, tr = 0;
        while (pl >= nt4 - tr) { pl -= nt4 - tr; tr++; }
        int tc = tr + pl;
        const float* E1 = Es + (size_t)tr * 4 * ND;
        const float* E2 = Es + (size_t)tc * 4 * ND;
        float acc[4][4] = {};
        for (int kk = 0; kk < ND; kk += 32) {
            int k = kk + lane;
            float e1[4], e2[4];
#pragma unroll
            for (int j = 0; j < 4; j++) { e1[j] = E1[j * ND + k]; e2[j] = E2[j * ND + k]; }
#pragma unroll
            for (int j = 0; j < 4; j++)
#pragma unroll
                for (int jj = 0; jj < 4; jj++)
                    acc[j][jj] = fmaf(e1[j], e2[jj], acc[j][jj]);
        }
#pragma unroll
        for (int j = 0; j < 4; j++)
#pragma unroll
            for (int jj = 0; jj < 4; jj++) {
#pragma unroll
                for (int o = 16; o; o >>= 1)
                    acc[j][jj] += __shfl_xor_sync(0xffffffffu, acc[j][jj], o);
            }
        if (lane == 0) {
#pragma unroll
            for (int j = 0; j < 4; j++)
#pragma unroll
                for (int jj = 0; jj < 4; jj++) {
                    float v = acc[j][jj];
                    out[(size_t)b * np + (tr * 4 + j) * ROWS + tc * 4 + jj] = v;
                    out[(size_t)b * np + (tc * 4 + jj) * ROWS + tr * 4 + j] = v;
                }
        }
    }
}

// ============================ bf16 cp.async pipelined GEMM (LDSM fragments) ============================
#define BM 128
#define BN 256
#define BK 32
#define ASZW (BM * 20)
#define STGW (ASZW + BN * 20)
#define STAGES 4
#define GEMM_SMEM (STAGES * STGW * 4)

__global__ void __launch_bounds__(256, 1) s_gemm(const __nv_bfloat16* __restrict__ Ah,
                                                 const __nv_bfloat16* __restrict__ Bh,
                                                 float* __restrict__ S) {
    extern __shared__ uint32_t smw[];
    uint32_t sb;
    asm("{ .reg .u64 t; cvta.to.shared.u64 t, %1; cvt.u32.u64 %0, t; }" : "=r"(sb) : "l"(smw));
    const int tid = threadIdx.x;
    const int wid = tid >> 5;
    const int lane = tid & 31;
    const int g = lane >> 2;
    const int t = lane & 3;
    const int wm = wid >> 2;
    const int wn = wid & 3;
    const int by = blockIdx.y;
    const int bx = blockIdx.x;
    const int m0 = by * BM;
    const int n0 = bx * BN;
    const bool pBlk = (bx == 40);
    const bool qBlk = (by >= 72);

    const int arow = tid >> 2;
    const int ac = tid & 3;
    const __nv_bfloat16* Agp = (qBlk ? (Ah + (size_t)9216 * ND + (size_t)(by - 72) * BM * ND)
                                     : (Ah + (size_t)m0 * ND)) + (size_t)arow * ND + ac * 8;
    const __nv_bfloat16* Bgp = (pBlk ? (Bh + (size_t)10240 * ND)
                                     : (Bh + (size_t)n0 * ND)) + (size_t)arow * ND + ac * 8;
    const uint32_t sA = sb + (uint32_t)(arow * 20 + ac * 4) * 4;
    const uint32_t sB = sb + (uint32_t)(ASZW + arow * 20 + ac * 4) * 4;

    // ldmatrix lane geometry
    const int alr = (lane & 7) + ((lane >> 3) & 1) * 8;
    const int ahf = (lane >> 4) & 1;
    const int blr = (lane & 7) + ((lane >> 4) & 1) * 8;
    const int bhf = (lane >> 3) & 1;
    const uint32_t aFrag = sb + (uint32_t)(((wm * 64 + alr) * 20) + ahf * 4) * 4;
    const uint32_t bFrag = sb + (uint32_t)((ASZW + (wn * 64 + blr) * 20) + bhf * 4) * 4;

    float cacc[4][8][4];
#pragma unroll
    for (int a = 0; a < 4; a++)
#pragma unroll
        for (int bb = 0; bb < 8; bb++)
#pragma unroll
            for (int cc = 0; cc < 4; cc++) cacc[a][bb][cc] = 0.f;

#define ISSUE(stg, kc) do {                                                    \
    uint32_t so = (uint32_t)(stg) * (STGW * 4);                                \
    _Pragma("unroll")                                                          \
    for (int j = 0; j < 2; j++)                                                \
        cpa16(sA + so + j * (64 * 20 * 4), Agp + (size_t)j * 64 * ND + (kc));  \
    _Pragma("unroll")                                                          \
    for (int j = 0; j < 4; j++)                                                \
        cpa16(sB + so + j * (64 * 20 * 4), Bgp + (size_t)j * 64 * ND + (kc));  \
} while (0)

#define COMPUTE(stg, ks) do {                                                  \
    const uint32_t so = (uint32_t)(stg) * (STGW * 4) + (ks) * 32;              \
    uint32_t af[4][4];                                                         \
    uint32_t bf[8][2];                                                         \
    _Pragma("unroll")                                                          \
    for (int mt = 0; mt < 4; mt++)                                             \
        ldsm_x4(af[mt][0], af[mt][1], af[mt][2], af[mt][3],                    \
                aFrag + so + mt * (16 * 20 * 4));                              \
    _Pragma("unroll")                                                          \
    for (int np = 0; np < 4; np++)                                             \
        ldsm_x4(bf[2 * np][0], bf[2 * np][1], bf[2 * np + 1][0],               \
                bf[2 * np + 1][1], bFrag + so + np * (16 * 20 * 4));           \
    _Pragma("unroll")                                                          \
    for (int mt = 0; mt < 4; mt++)                                             \
        _Pragma("unroll")                                                      \
        for (int nt = 0; nt < 8; nt++)                                         \
            mma_bf16(cacc[mt][nt], af[mt], bf[nt]);                            \
} while (0)

    ISSUE(0, 0);  asm volatile("cp.async.commit_group;" ::: "memory");
    ISSUE(1, 32); asm volatile("cp.async.commit_group;" ::: "memory");
    ISSUE(2, 64); asm volatile("cp.async.commit_group;" ::: "memory");

#pragma unroll 1
    for (int c = 0; c < 32; c++) {
        asm volatile("cp.async.wait_group 2;" ::: "memory");
        __syncthreads();
        COMPUTE(c & 3, 0);
        COMPUTE(c & 3, 1);
        if (c < 29) ISSUE((c + 3) & 3, (c + 3) * BK);
        asm volatile("cp.async.commit_group;" ::: "memory");
    }

    if (pBlk && qBlk) return;

    if (!pBlk && !qBlk) {
#pragma unroll
        for (int mt = 0; mt < 4; mt++) {
            int m = m0 + wm * 64 + mt * 16 + g;
#pragma unroll
            for (int nt = 0; nt < 8; nt++) {
                int n = n0 + wn * 64 + nt * 8 + 2 * t;
                float v0 = cacc[mt][nt][0]; v0 = (v0 >= 0.f) ? v0 : 0.1f * v0;
                float v1 = cacc[mt][nt][1]; v1 = (v1 >= 0.f) ? v1 : 0.1f * v1;
                float v2 = cacc[mt][nt][2]; v2 = (v2 >= 0.f) ? v2 : 0.1f * v2;
                float v3 = cacc[mt][nt][3]; v3 = (v3 >= 0.f) ? v3 : 0.1f * v3;
                __stcs(S + (size_t)n * MT + m, v0);
                __stcs(S + (size_t)(n + 1) * MT + m, v1);
                __stcs(S + (size_t)n * MT + m + 8, v2);
                __stcs(S + (size_t)(n + 1) * MT + m + 8, v3);
            }
        }
    } else if (pBlk) {
#pragma unroll
        for (int mt = 0; mt < 4; mt++) {
            int m = m0 + wm * 64 + mt * 16 + g;
#pragma unroll
            for (int nt = 0; nt < 8; nt++) {
                int i = wn * 64 + nt * 8 + 2 * t;
                __stcs(g_P + (size_t)i * MT + m, cacc[mt][nt][0]);
                __stcs(g_P + (size_t)(i + 1) * MT + m, cacc[mt][nt][1]);
                __stcs(g_P + (size_t)i * MT + m + 8, cacc[mt][nt][2]);
                __stcs(g_P + (size_t)(i + 1) * MT + m + 8, cacc[mt][nt][3]);
            }
        }
    } else {
#pragma unroll
        for (int mt = 0; mt < 4; mt++) {
            int b = (by - 72) * BM + wm * 64 + mt * 16 + g;
#pragma unroll
            for (int nt = 0; nt < 8; nt++) {
                int n = n0 + wn * 64 + nt * 8 + 2 * t;
                __stcs(g_Q + (size_t)b * NT + n, cacc[mt][nt][0]);
                __stcs(g_Q + (size_t)b * NT + n + 1, cacc[mt][nt][1]);
                __stcs(g_Q + (size_t)(b + 8) * NT + n, cacc[mt][nt][2]);
                __stcs(g_Q + (size_t)(b + 8) * NT + n + 1, cacc[mt][nt][3]);
            }
        }
    }
#undef ISSUE
#undef COMPUTE
}

// ============================ per-pair epilogue: single-round warp-specialized ============================
// word offsets: FS 0 (1600, [r][l] stride 41) | Am 1600 (40x44, [l][r]) | Cm 3360 (36x44, [r][l])
//               Hs 4944 (40x40) | Gs 6544 (36x36) | w2p1 7840 (40x10) | w2p2 8240 (36x6)
#define EPI_WORDS 8456
#define EPI_SMEM (EPI_WORDS * 4)

__global__ void __launch_bounds__(128) pair_epilogue(const float* __restrict__ S,
                                                     float* __restrict__ out) {
    extern __shared__ float sh[];
    __shared__ __align__(16) float Pb[NR];
    __shared__ __align__(16) float Qi[NL];
    __shared__ float rnl[NR], cnl[NL], s1s[NL], s2s[NR];
    __shared__ float w12a[NL], w12b[NR];
    float* FS = sh;
    float* Am = sh + 1600;
    float* Cm = sh + 3360;
    float* Hs = sh + 4944;
    float* Gs = sh + 6544;
    float* w2p1 = sh + 7840;
    float* w2p2 = sh + 8240;
    const int i = blockIdx.x, b = blockIdx.y, tid = threadIdx.x;

    const float* Sp = S + (size_t)i * NL * MT + (size_t)b * NR;
    for (int idx = tid; idx < NR * NL; idx += 128) {
        int l = idx / NR, r = idx - l * NR;
        FS[r * 41 + l] = __ldcs(Sp + (size_t)l * MT + r);
    }
    for (int idx = tid; idx < NR * NR; idx += 128) Gs[idx] = g_G[(size_t)b * (NR * NR) + idx];
    for (int idx = tid; idx < NL * NL; idx += 128) Hs[idx] = g_H[(size_t)i * (NL * NL) + idx];
    if (tid < NR) Pb[tid] = g_P[(size_t)i * MT + b * NR + tid];
    else if (tid >= 64 && tid < 64 + NL) Qi[tid - 64] = g_Q[(size_t)b * NT + i * NL + (tid - 64)];
    __syncthreads();

    if (tid < NL) {                         // column norms over r -> lambda/cn
        int l = tid; float s = 0.f;
#pragma unroll
        for (int r = 0; r < NR; r++) { float v = FS[r * 41 + l]; s = fmaf(v, v, s); }
        cnl[l] = LAMS / (sqrtf(s) + EPSF);
    } else if (tid >= 64 && tid < 64 + NR) { // row norms over l -> lambda/rn
        int r = tid - 64; float s = 0.f;
#pragma unroll
        for (int l = 0; l < NL; l++) { float v = FS[r * 41 + l]; s = fmaf(v, v, s); }
        rnl[r] = LAMS / (sqrtf(s) + EPSF);
    }
    __syncthreads();

    for (int idx = tid; idx < NR * NL; idx += 128) {
        int l = idx / NR, r = idx - l * NR;
        float v = FS[r * 41 + l];
        Am[l * 44 + r] = __expf(v * rnl[r]);      // [l][r]
        Cm[r * 44 + l] = __expf(v * cnl[l]);      // [r][l]
    }
    __syncthreads();

    // ---- single-round tasks: tid 0-44 M1(8lx4r), 45-54 w12a, 55-63 w12b, 64-108 M2(4rx8l) ----
    if (tid < 45) {
        int lg = tid / 9, rg = tid - lg * 9;
        const float* Ab = Am + lg * 8 * 44;
        const float* Gb = Gs + rg * 4;
        float4 acc[8], st[8];
#pragma unroll
        for (int j = 0; j < 8; j++) { acc[j] = make_float4(0.f, 0.f, 0.f, 0.f); st[j] = acc[j]; }
#pragma unroll
        for (int rp4 = 0; rp4 < 9; rp4++) {
            float4 g0 = *(const float4*)(Gb + (rp4 * 4 + 0) * 36);
            float4 g1 = *(const float4*)(Gb + (rp4 * 4 + 1) * 36);
            float4 g2 = *(const float4*)(Gb + (rp4 * 4 + 2) * 36);
            float4 g3 = *(const float4*)(Gb + (rp4 * 4 + 3) * 36);
#pragma unroll
            for (int j = 0; j < 8; j++) {
                float4 a = *(const float4*)(Ab + j * 44 + rp4 * 4);
                if (rp4 == rg) st[j] = a;
                acc[j].x = fmaf(a.x, g0.x, acc[j].x); acc[j].y = fmaf(a.x, g0.y, acc[j].y);
                acc[j].z = fmaf(a.x, g0.z, acc[j].z); acc[j].w = fmaf(a.x, g0.w, acc[j].w);
                acc[j].x = fmaf(a.y, g1.x, acc[j].x); acc[j].y = fmaf(a.y, g1.y, acc[j].y);
                acc[j].z = fmaf(a.y, g1.z, acc[j].z); acc[j].w = fmaf(a.y, g1.w, acc[j].w);
                acc[j].x = fmaf(a.z, g2.x, acc[j].x); acc[j].y = fmaf(a.z, g2.y, acc[j].y);
                acc[j].z = fmaf(a.z, g2.z, acc[j].z); acc[j].w = fmaf(a.z, g2.w, acc[j].w);
                acc[j].x = fmaf(a.w, g3.x, acc[j].x); acc[j].y = fmaf(a.w, g3.y, acc[j].y);
                acc[j].z = fmaf(a.w, g3.z, acc[j].z); acc[j].w = fmaf(a.w, g3.w, acc[j].w);
            }
        }
#pragma unroll
        for (int j = 0; j < 8; j++)
            w2p1[(lg * 8 + j) * 10 + rg] = acc[j].x * st[j].x + acc[j].y * st[j].y +
                                           acc[j].z * st[j].z + acc[j].w * st[j].w;
    } else if (tid < 55) {
        int lq = tid - 45;
        float a0 = 0.f, a1 = 0.f, a2 = 0.f, a3 = 0.f;
#pragma unroll
        for (int rq = 0; rq < 9; rq++) {
            float4 p = *(const float4*)(Pb + rq * 4);
            float4 x0 = *(const float4*)(Am + (lq * 4 + 0) * 44 + rq * 4);
            float4 x1 = *(const float4*)(Am + (lq * 4 + 1) * 44 + rq * 4);
            float4 x2 = *(const float4*)(Am + (lq * 4 + 2) * 44 + rq * 4);
            float4 x3 = *(const float4*)(Am + (lq * 4 + 3) * 44 + rq * 4);
            a0 = fmaf(x0.x, p.x, fmaf(x0.y, p.y, fmaf(x0.z, p.z, fmaf(x0.w, p.w, a0))));
            a1 = fmaf(x1.x, p.x, fmaf(x1.y, p.y, fmaf(x1.z, p.z, fmaf(x1.w, p.w, a1))));
            a2 = fmaf(x2.x, p.x, fmaf(x2.y, p.y, fmaf(x2.z, p.z, fmaf(x2.w, p.w, a2))));
            a3 = fmaf(x3.x, p.x, fmaf(x3.y, p.y, fmaf(x3.z, p.z, fmaf(x3.w, p.w, a3))));
        }
        w12a[lq * 4 + 0] = a0; w12a[lq * 4 + 1] = a1;
        w12a[lq * 4 + 2] = a2; w12a[lq * 4 + 3] = a3;
    } else if (tid < 64) {
        int rq = tid - 55;
        float a0 = 0.f, a1 = 0.f, a2 = 0.f, a3 = 0.f;
#pragma unroll
        for (int lq = 0; lq < 10; lq++) {
            float4 q = *(const float4*)(Qi + lq * 4);
            float4 x0 = *(const float4*)(Cm + (rq * 4 + 0) * 44 + lq * 4);
            float4 x1 = *(const float4*)(Cm + (rq * 4 + 1) * 44 + lq * 4);
            float4 x2 = *(const float4*)(Cm + (rq * 4 + 2) * 44 + lq * 4);
            float4 x3 = *(const float4*)(Cm + (rq * 4 + 3) * 44 + lq * 4);
            a0 = fmaf(x0.x, q.x, fmaf(x0.y, q.y, fmaf(x0.z, q.z, fmaf(x0.w, q.w, a0))));
            a1 = fmaf(x1.x, q.x, fmaf(x1.y, q.y, fmaf(x1.z, q.z, fmaf(x1.w, q.w, a1))));
            a2 = fmaf(x2.x, q.x, fmaf(x2.y, q.y, fmaf(x2.z, q.z, fmaf(x2.w, q.w, a2))));
            a3 = fmaf(x3.x, q.x, fmaf(x3.y, q.y, fmaf(x3.z, q.z, fmaf(x3.w, q.w, a3))));
        }
        w12b[rq * 4 + 0] = a0; w12b[rq * 4 + 1] = a1;
        w12b[rq * 4 + 2] = a2; w12b[rq * 4 + 3] = a3;
    } else if (tid < 109) {
        int idx = tid - 64;
        int rg = idx / 5, lg = idx - rg * 5;
        const float* Cb = Cm + rg * 4 * 44;
        const float* Hb = Hs + lg * 8;
        float4 aclo[4], achi[4], stlo[4], sthi[4];
#pragma unroll
        for (int j = 0; j < 4; j++) {
            aclo[j] = make_float4(0.f, 0.f, 0.f, 0.f);
            achi[j] = aclo[j]; stlo[j] = aclo[j]; sthi[j] = aclo[j];
        }
#pragma unroll
        for (int lp4 = 0; lp4 < 10; lp4++) {
            float4 h0l = *(const float4*)(Hb + (lp4 * 4 + 0) * 40);
            float4 h0h = *(const float4*)(Hb + (lp4 * 4 + 0) * 40 + 4);
            float4 h1l = *(const float4*)(Hb + (lp4 * 4 + 1) * 40);
            float4 h1h = *(const float4*)(Hb + (lp4 * 4 + 1) * 40 + 4);
            float4 h2l = *(const float4*)(Hb + (lp4 * 4 + 2) * 40);
            float4 h2h = *(const float4*)(Hb + (lp4 * 4 + 2) * 40 + 4);
            float4 h3l = *(const float4*)(Hb + (lp4 * 4 + 3) * 40);
            float4 h3h = *(const float4*)(Hb + (lp4 * 4 + 3) * 40 + 4);
#pragma unroll
            for (int j = 0; j < 4; j++) {
                float4 c = *(const float4*)(Cb + j * 44 + lp4 * 4);
                if (lp4 == 2 * lg) stlo[j] = c;
                if (lp4 == 2 * lg + 1) sthi[j] = c;
                aclo[j].x = fmaf(c.x, h0l.x, aclo[j].x); aclo[j].y = fmaf(c.x, h0l.y, aclo[j].y);
                aclo[j].z = fmaf(c.x, h0l.z, aclo[j].z); aclo[j].w = fmaf(c.x, h0l.w, aclo[j].w);
                aclo[j].x = fmaf(c.y, h1l.x, aclo[j].x); aclo[j].y = fmaf(c.y, h1l.y, aclo[j].y);
                aclo[j].z = fmaf(c.y, h1l.z, aclo[j].z); aclo[j].w = fmaf(c.y, h1l.w, aclo[j].w);
                aclo[j].x = fmaf(c.z, h2l.x, aclo[j].x); aclo[j].y = fmaf(c.z, h2l.y, aclo[j].y);
                aclo[j].z = fmaf(c.z, h2l.z, aclo[j].z); aclo[j].w = fmaf(c.z, h2l.w, aclo[j].w);
                aclo[j].x = fmaf(c.w, h3l.x, aclo[j].x); aclo[j].y = fmaf(c.w, h3l.y, aclo[j].y);
                aclo[j].z = fmaf(c.w, h3l.z, aclo[j].z); aclo[j].w = fmaf(c.w, h3l.w, aclo[j].w);
                achi[j].x = fmaf(c.x, h0h.x, achi[j].x); achi[j].y = fmaf(c.x, h0h.y, achi[j].y);
                achi[j].z = fmaf(c.x, h0h.z, achi[j].z); achi[j].w = fmaf(c.x, h0h.w, achi[j].w);
                achi[j].x = fmaf(c.y, h1h.x, achi[j].x); achi[j].y = fmaf(c.y, h1h.y, achi[j].y);
                achi[j].z = fmaf(c.y, h1h.z, achi[j].z); achi[j].w = fmaf(c.y, h1h.w, achi[j].w);
                achi[j].x = fmaf(c.z, h2h.x, achi[j].x); achi[j].y = fmaf(c.z, h2h.y, achi[j].y);
                achi[j].z = fmaf(c.z, h2h.z, achi[j].z); achi[j].w = fmaf(c.z, h2h.w, achi[j].w);
                achi[j].x = fmaf(c.w, h3h.x, achi[j].x); achi[j].y = fmaf(c.w, h3h.y, achi[j].y);
                achi[j].z = fmaf(c.w, h3h.z, achi[j].z); achi[j].w = fmaf(c.w, h3h.w, achi[j].w);
            }
        }
#pragma unroll
        for (int j = 0; j < 4; j++)
            w2p2[(rg * 4 + j) * 6 + lg] =
                aclo[j].x * stlo[j].x + aclo[j].y * stlo[j].y +
                aclo[j].z * stlo[j].z + aclo[j].w * stlo[j].w +
                achi[j].x * sthi[j].x + achi[j].y * sthi[j].y +
                achi[j].z * sthi[j].z + achi[j].w * sthi[j].w;
    }
    __syncthreads();

    if (tid < NL) {                          // t2i: word l
        int l = tid; float w2 = 0.f;
#pragma unroll
        for (int k = 0; k < 9; k++) w2 += w2p1[l * 10 + k];
        float den = fmaxf(g_w1t[i] * sqrtf(fmaxf(w2, 0.f)), EPSF);
        s1s[l] = __fdividef(w12a[l], den);
    } else if (tid >= 64 && tid < 64 + NR) { // i2t: region r
        int r = tid - 64; float w2 = 0.f;
#pragma unroll
        for (int k = 0; k < 5; k++) w2 += w2p2[r * 6 + k];
        float den = fmaxf(g_w1i[b] * sqrtf(fmaxf(w2, 0.f)), EPSF);
        s2s[r] = __fdividef(w12b[r], den);
    }
    __syncthreads();

    if (tid == 0) {
        float m1 = 0.f, m2 = 0.f;
#pragma unroll
        for (int l = 0; l < NL; l++) m1 += s1s[l];
#pragma unroll
        for (int r = 0; r < NR; r++) m2 += s2s[r];
        out[(size_t)b * NB + i] = g_base[b * NB + i] + m1 * (1.f / NL) + m2 * (1.f / NR);
    }
}

// ============================ launch ============================
extern "C" void kernel_launch(void* const* d_in, const int* in_sizes, int n_in,
                              void* d_out, int out_size) {
    (void)in_sizes; (void)n_in; (void)out_size;
    const float* pool_img = (const float*)d_in[0];
    const float* img_emb  = (const float*)d_in[1];
    const float* pool_txt = (const float*)d_in[2];
    const float* cap_emb  = (const float*)d_in[3];
    float* out = (float*)d_out;

    cudaFuncSetAttribute((const void*)gram_kernel,
                         cudaFuncAttributeMaxDynamicSharedMemorySize, NL * ND * 4);
    cudaFuncSetAttribute((const void*)s_gemm,
                         cudaFuncAttributeMaxDynamicSharedMemorySize, GEMM_SMEM);
    cudaFuncSetAttribute((const void*)pair_epilogue,
                         cudaFuncAttributeMaxDynamicSharedMemorySize, EPI_SMEM);

    float* dS = nullptr;
    cudaGetSymbolAddress((void**)&dS, g_S);
    __nv_bfloat16* dAh = nullptr; cudaGetSymbolAddress((void**)&dAh, g_Ah);
    __nv_bfloat16* dBh = nullptr; cudaGetSymbolAddress((void**)&dBh, g_Bh);

    // order: s_gemm stays at launch index 3 (profiled slot)
    cvt_kernel<<<9984, 256>>>(img_emb, pool_img, cap_emb, pool_txt);
    gram_kernel<<<NB, 256, NR * ND * 4>>>(img_emb, NR, 0);
    gram_kernel<<<NB, 256, NL * ND * 4>>>(cap_emb, NL, 1);
    s_gemm<<<dim3(41, 74), 256, GEMM_SMEM>>>(dAh, dBh, dS);
    norm_kernel<<<64, 256>>>(pool_img, pool_txt);
    sgemm_tn<<<dim3(NB / 64, NB / 64), 256>>>(pool_img, pool_txt, NB, NB, ND);
    pair_epilogue<<<dim3(NB, NB), 128, EPI_SMEM>>>(dS, out);
}

// round 11
// speedup vs baseline: 1.3743x; 1.3743x over previous
#include <cuda_runtime.h>
#include <cuda_bf16.h>
#include <math.h>
#include <cstdint>

#define NB 256
#define NR 36
#define NL 40
#define ND 1024
#define MT (NB * NR)   /* 9216  */
#define NT (NB * NL)   /* 10240 */
#define EPSF 1e-8f
#define LAMS 9.0f

#define MROWS 9472     /* 9216 img rows + 256 pool_img */
#define NROWS 10496    /* 10240 cap rows + 256 pool_txt */

// ---- scratch (device globals; no allocation allowed) ----
__device__ float g_S[(size_t)MT * NT];           // S^T[n][m], leaky-relu'd (378MB)
__device__ __nv_bfloat16 g_Ah[(size_t)MROWS * ND];  // bf16 img_emb ++ pool_img
__device__ __nv_bfloat16 g_Bh[(size_t)NROWS * ND];  // bf16 cap_emb ++ pool_txt
__device__ float g_P[NB * NB * NR];
__device__ float g_Q[NB * NB * NL];
__device__ float g_G[NB * NR * NR];
__device__ float g_H[NB * NL * NL];
__device__ float g_base[NB * NB];
__device__ float g_w1i[NB];
__device__ float g_w1t[NB];

__device__ __forceinline__ float4 ldg4(const float* p) {
    return *reinterpret_cast<const float4*>(p);
}
__device__ __forceinline__ uint32_t pack_bf2(float x, float y) {
    __nv_bfloat162 h = __float22bfloat162_rn(make_float2(x, y));
    return *reinterpret_cast<uint32_t*>(&h);
}
__device__ __forceinline__ void mma_bf16(float* c, const uint32_t* a, const uint32_t* b) {
    asm volatile(
        "mma.sync.aligned.m16n8k16.row.col.f32.bf16.bf16.f32 "
        "{%0,%1,%2,%3}, {%4,%5,%6,%7}, {%8,%9}, {%0,%1,%2,%3};"
        : "+f"(c[0]), "+f"(c[1]), "+f"(c[2]), "+f"(c[3])
        : "r"(a[0]), "r"(a[1]), "r"(a[2]), "r"(a[3]), "r"(b[0]), "r"(b[1]));
}
__device__ __forceinline__ void cpa16(uint32_t saddr, const void* gaddr) {
    asm volatile("cp.async.ca.shared.global [%0], [%1], 16;"
                 :: "r"(saddr), "l"(gaddr) : "memory");
}
__device__ __forceinline__ void ldsm_x4(uint32_t& r0, uint32_t& r1, uint32_t& r2,
                                        uint32_t& r3, uint32_t addr) {
    asm volatile("ldmatrix.sync.aligned.m8n8.x4.shared.b16 {%0,%1,%2,%3}, [%4];"
                 : "=r"(r0), "=r"(r1), "=r"(r2), "=r"(r3) : "r"(addr));
}

// ============================ bf16 conversion (augmented operands) ============================
__global__ void cvt_kernel(const float* __restrict__ img, const float* __restrict__ pimg,
                           const float* __restrict__ cap, const float* __restrict__ ptxt) {
    size_t g8 = (size_t)blockIdx.x * 256 + threadIdx.x;
    const size_t A8 = (size_t)MROWS * (ND / 8);
    const float* src;
    uint32_t* dst;
    if (g8 < A8) {
        size_t off = g8 * 8;
        size_t row = off >> 10, col = off & 1023;
        src = (row < 9216) ? (img + row * ND + col) : (pimg + (row - 9216) * ND + col);
        dst = reinterpret_cast<uint32_t*>(g_Ah) + g8 * 4;
    } else {
        size_t h8 = g8 - A8;
        size_t off = h8 * 8;
        size_t row = off >> 10, col = off & 1023;
        src = (row < 10240) ? (cap + row * ND + col) : (ptxt + (row - 10240) * ND + col);
        dst = reinterpret_cast<uint32_t*>(g_Bh) + h8 * 4;
    }
    float4 x = ldg4(src), y = ldg4(src + 4);
    *reinterpret_cast<uint4*>(dst) =
        make_uint4(pack_bf2(x.x, x.y), pack_bf2(x.z, x.w),
                   pack_bf2(y.x, y.y), pack_bf2(y.z, y.w));
}

// ============================ precompute kernels ============================
__global__ void norm_kernel(const float* __restrict__ pi, const float* __restrict__ pt) {
    int w = blockIdx.x * 8 + (threadIdx.x >> 5);
    int lane = threadIdx.x & 31;
    const float* src = (w < NB) ? (pi + (size_t)w * ND) : (pt + (size_t)(w - NB) * ND);
    float s = 0.f;
    for (int j = lane; j < ND; j += 32) { float v = src[j]; s = fmaf(v, v, s); }
#pragma unroll
    for (int o = 16; o; o >>= 1) s += __shfl_down_sync(0xffffffffu, s, o);
    if (lane == 0) {
        float r = sqrtf(s);
        if (w < NB) g_w1i[w] = r; else g_w1t[w - NB] = r;
    }
}

__global__ void sgemm_tn(const float* __restrict__ A, const float* __restrict__ Bm,
                         int M, int N, int K) {
    float* C = g_base;
    __shared__ float As[16 * 64];
    __shared__ float Bs[16 * 64];
    int tid = threadIdx.x;
    int tx = tid & 15, ty = tid >> 4;
    int m0 = blockIdx.y * 64, n0 = blockIdx.x * 64;
    int row = tid >> 2, q = tid & 3;
    float acc[4][4] = {};
    for (int k0 = 0; k0 < K; k0 += 16) {
        float4 a = ldg4(A + (size_t)(m0 + row) * K + k0 + q * 4);
        float4 bb = ldg4(Bm + (size_t)(n0 + row) * K + k0 + q * 4);
        As[(q * 4 + 0) * 64 + row] = a.x;  As[(q * 4 + 1) * 64 + row] = a.y;
        As[(q * 4 + 2) * 64 + row] = a.z;  As[(q * 4 + 3) * 64 + row] = a.w;
        Bs[(q * 4 + 0) * 64 + row] = bb.x; Bs[(q * 4 + 1) * 64 + row] = bb.y;
        Bs[(q * 4 + 2) * 64 + row] = bb.z; Bs[(q * 4 + 3) * 64 + row] = bb.w;
        __syncthreads();
#pragma unroll
        for (int k = 0; k < 16; k++) {
            float4 av = *(const float4*)(As + k * 64 + ty * 4);
            float4 bv = *(const float4*)(Bs + k * 64 + tx * 4);
            float aa[4] = {av.x, av.y, av.z, av.w};
            float bw[4] = {bv.x, bv.y, bv.z, bv.w};
#pragma unroll
            for (int ii = 0; ii < 4; ii++)
#pragma unroll
                for (int jj = 0; jj < 4; jj++)
                    acc[ii][jj] = fmaf(aa[ii], bw[jj], acc[ii][jj]);
        }
        __syncthreads();
    }
#pragma unroll
    for (int ii = 0; ii < 4; ii++)
#pragma unroll
        for (int jj = 0; jj < 4; jj++)
            C[(size_t)(m0 + ty * 4 + ii) * N + n0 + tx * 4 + jj] = acc[ii][jj];
}

// per-row Gram, 4x4 register-blocked, symmetric
__global__ void gram_kernel(const float* __restrict__ emb, int ROWS, int which) {
    extern __shared__ float Es[];
    float* out = which ? g_H : g_G;
    int b = blockIdx.x, tid = threadIdx.x;
    int wid = tid >> 5, lane = tid & 31;
    int n = ROWS * ND;
    int np = ROWS * ROWS;
    for (int idx = tid; idx < n; idx += 256) Es[idx] = emb[(size_t)b * n + idx];
    __syncthreads();
    int nt4 = ROWS / 4;
    int count = nt4 * (nt4 + 1) / 2;
    for (int p = wid; p < count; p += 8) {
        int pl = p, tr = 0;
        while (pl >= nt4 - tr) { pl -= nt4 - tr; tr++; }
        int tc = tr + pl;
        const float* E1 = Es + (size_t)tr * 4 * ND;
        const float* E2 = Es + (size_t)tc * 4 * ND;
        float acc[4][4] = {};
        for (int kk = 0; kk < ND; kk += 32) {
            int k = kk + lane;
            float e1[4], e2[4];
#pragma unroll
            for (int j = 0; j < 4; j++) { e1[j] = E1[j * ND + k]; e2[j] = E2[j * ND + k]; }
#pragma unroll
            for (int j = 0; j < 4; j++)
#pragma unroll
                for (int jj = 0; jj < 4; jj++)
                    acc[j][jj] = fmaf(e1[j], e2[jj], acc[j][jj]);
        }
#pragma unroll
        for (int j = 0; j < 4; j++)
#pragma unroll
            for (int jj = 0; jj < 4; jj++) {
#pragma unroll
                for (int o = 16; o; o >>= 1)
                    acc[j][jj] += __shfl_xor_sync(0xffffffffu, acc[j][jj], o);
            }
        if (lane == 0) {
#pragma unroll
            for (int j = 0; j < 4; j++)
#pragma unroll
                for (int jj = 0; jj < 4; jj++) {
                    float v = acc[j][jj];
                    out[(size_t)b * np + (tr * 4 + j) * ROWS + tc * 4 + jj] = v;
                    out[(size_t)b * np + (tc * 4 + jj) * ROWS + tr * 4 + j] = v;
                }
        }
    }
}

// ============================ bf16 cp.async GEMM, BM=128 BN=128, 2 CTAs/SM ============================
#define BM 128
#define BN 128
#define BK 32
#define ASZW (BM * 20)              /* 2560 words */
#define STGW (ASZW + BN * 20)       /* 5120 words = 20480 B */
#define STAGES 4
#define GEMM_SMEM (STAGES * STGW * 4)   /* 81920 B */

__global__ void __launch_bounds__(256, 2) s_gemm(const __nv_bfloat16* __restrict__ Ah,
                                                 const __nv_bfloat16* __restrict__ Bh,
                                                 float* __restrict__ S) {
    extern __shared__ uint32_t smw[];
    uint32_t sb;
    asm("{ .reg .u64 t; cvta.to.shared.u64 t, %1; cvt.u32.u64 %0, t; }" : "=r"(sb) : "l"(smw));
    const int tid = threadIdx.x;
    const int wid = tid >> 5;
    const int lane = tid & 31;
    const int g = lane >> 2;
    const int t = lane & 3;
    const int wm = wid >> 2;        // 0..1  (m 64-half)
    const int wn = wid & 3;         // 0..3  (n 32-quarter)
    const int by = blockIdx.y;
    const int bx = blockIdx.x;
    const int m0 = by * BM;
    const int n0 = bx * BN;
    const bool pBlk = (bx >= 80);
    const bool qBlk = (by >= 72);

    const int arow = tid >> 2;      // 0..63
    const int ac = tid & 3;
    const __nv_bfloat16* Agp = (qBlk ? (Ah + (size_t)9216 * ND + (size_t)(by - 72) * BM * ND)
                                     : (Ah + (size_t)m0 * ND)) + (size_t)arow * ND + ac * 8;
    const __nv_bfloat16* Bgp = (pBlk ? (Bh + (size_t)10240 * ND + (size_t)(bx - 80) * BN * ND)
                                     : (Bh + (size_t)n0 * ND)) + (size_t)arow * ND + ac * 8;
    const uint32_t sA = sb + (uint32_t)(arow * 20 + ac * 4) * 4;
    const uint32_t sB = sb + (uint32_t)(ASZW + arow * 20 + ac * 4) * 4;

    // ldmatrix lane geometry (identical mapping to R9, new base offsets)
    const int alr = (lane & 7) + ((lane >> 3) & 1) * 8;
    const int ahf = (lane >> 4) & 1;
    const int blr = (lane & 7) + ((lane >> 4) & 1) * 8;
    const int bhf = (lane >> 3) & 1;
    const uint32_t aFrag = sb + (uint32_t)(((wm * 64 + alr) * 20) + ahf * 4) * 4;
    const uint32_t bFrag = sb + (uint32_t)((ASZW + (wn * 32 + blr) * 20) + bhf * 4) * 4;

    float cacc[4][4][4];
#pragma unroll
    for (int a = 0; a < 4; a++)
#pragma unroll
        for (int bb = 0; bb < 4; bb++)
#pragma unroll
            for (int cc = 0; cc < 4; cc++) cacc[a][bb][cc] = 0.f;

#define ISSUE(stg, kc) do {                                                    \
    uint32_t so = (uint32_t)(stg) * (STGW * 4);                                \
    _Pragma("unroll")                                                          \
    for (int j = 0; j < 2; j++)                                                \
        cpa16(sA + so + j * (64 * 20 * 4), Agp + (size_t)j * 64 * ND + (kc));  \
    _Pragma("unroll")                                                          \
    for (int j = 0; j < 2; j++)                                                \
        cpa16(sB + so + j * (64 * 20 * 4), Bgp + (size_t)j * 64 * ND + (kc));  \
} while (0)

#define COMPUTE(stg, ks) do {                                                  \
    const uint32_t so = (uint32_t)(stg) * (STGW * 4) + (ks) * 32;              \
    uint32_t af[4][4];                                                         \
    uint32_t bf[4][2];                                                         \
    _Pragma("unroll")                                                          \
    for (int mt = 0; mt < 4; mt++)                                             \
        ldsm_x4(af[mt][0], af[mt][1], af[mt][2], af[mt][3],                    \
                aFrag + so + mt * (16 * 20 * 4));                              \
    _Pragma("unroll")                                                          \
    for (int np = 0; np < 2; np++)                                             \
        ldsm_x4(bf[2 * np][0], bf[2 * np][1], bf[2 * np + 1][0],               \
                bf[2 * np + 1][1], bFrag + so + np * (16 * 20 * 4));           \
    _Pragma("unroll")                                                          \
    for (int mt = 0; mt < 4; mt++)                                             \
        _Pragma("unroll")                                                      \
        for (int nt = 0; nt < 4; nt++)                                         \
            mma_bf16(cacc[mt][nt], af[mt], bf[nt]);                            \
} while (0)

    ISSUE(0, 0);  asm volatile("cp.async.commit_group;" ::: "memory");
    ISSUE(1, 32); asm volatile("cp.async.commit_group;" ::: "memory");
    ISSUE(2, 64); asm volatile("cp.async.commit_group;" ::: "memory");

#pragma unroll 1
    for (int c = 0; c < 32; c++) {
        asm volatile("cp.async.wait_group 2;" ::: "memory");
        __syncthreads();
        COMPUTE(c & 3, 0);
        COMPUTE(c & 3, 1);
        if (c < 29) ISSUE((c + 3) & 3, (c + 3) * BK);
        asm volatile("cp.async.commit_group;" ::: "memory");
    }

    if (pBlk && qBlk) return;

    if (!pBlk && !qBlk) {
#pragma unroll
        for (int mt = 0; mt < 4; mt++) {
            int m = m0 + wm * 64 + mt * 16 + g;
#pragma unroll
            for (int nt = 0; nt < 4; nt++) {
                int n = n0 + wn * 32 + nt * 8 + 2 * t;
                float v0 = cacc[mt][nt][0]; v0 = (v0 >= 0.f) ? v0 : 0.1f * v0;
                float v1 = cacc[mt][nt][1]; v1 = (v1 >= 0.f) ? v1 : 0.1f * v1;
                float v2 = cacc[mt][nt][2]; v2 = (v2 >= 0.f) ? v2 : 0.1f * v2;
                float v3 = cacc[mt][nt][3]; v3 = (v3 >= 0.f) ? v3 : 0.1f * v3;
                __stcs(S + (size_t)n * MT + m, v0);
                __stcs(S + (size_t)(n + 1) * MT + m, v1);
                __stcs(S + (size_t)n * MT + m + 8, v2);
                __stcs(S + (size_t)(n + 1) * MT + m + 8, v3);
            }
        }
    } else if (pBlk) {
#pragma unroll
        for (int mt = 0; mt < 4; mt++) {
            int m = m0 + wm * 64 + mt * 16 + g;
#pragma unroll
            for (int nt = 0; nt < 4; nt++) {
                int i = (bx - 80) * BN + wn * 32 + nt * 8 + 2 * t;
                __stcs(g_P + (size_t)i * MT + m, cacc[mt][nt][0]);
                __stcs(g_P + (size_t)(i + 1) * MT + m, cacc[mt][nt][1]);
                __stcs(g_P + (size_t)i * MT + m + 8, cacc[mt][nt][2]);
                __stcs(g_P + (size_t)(i + 1) * MT + m + 8, cacc[mt][nt][3]);
            }
        }
    } else {
#pragma unroll
        for (int mt = 0; mt < 4; mt++) {
            int b = (by - 72) * BM + wm * 64 + mt * 16 + g;
#pragma unroll
            for (int nt = 0; nt < 4; nt++) {
                int n = n0 + wn * 32 + nt * 8 + 2 * t;
                __stcs(g_Q + (size_t)b * NT + n, cacc[mt][nt][0]);
                __stcs(g_Q + (size_t)b * NT + n + 1, cacc[mt][nt][1]);
                __stcs(g_Q + (size_t)(b + 8) * NT + n, cacc[mt][nt][2]);
                __stcs(g_Q + (size_t)(b + 8) * NT + n + 1, cacc[mt][nt][3]);
            }
        }
    }
#undef ISSUE
#undef COMPUTE
}

// ============================ per-pair epilogue (R7 proven version, unchanged) ============================
// word offsets: FS 0 (1600, stride 41) | Am 1600 (40x44) | Cm 3360 (36x44)
//               Hs 4944 (40x40) | Gs 6544 (36x36) | w2p1 7840 (40x9) | w2p2 8200 (36x10)
#define EPI_WORDS 8560
#define EPI_SMEM (EPI_WORDS * 4)

__global__ void __launch_bounds__(128) pair_epilogue(const float* __restrict__ S,
                                                     float* __restrict__ out) {
    extern __shared__ float sh[];
    __shared__ float Pb[NR], Qi[NL], rnl[NR], cnl[NL], s1s[NL], s2s[NR];
    float* FS = sh;
    float* Am = sh + 1600;
    float* Cm = sh + 3360;
    float* Hs = sh + 4944;
    float* Gs = sh + 6544;
    float* w2p1 = sh + 7840;
    float* w2p2 = sh + 8200;
    const int i = blockIdx.x, b = blockIdx.y, tid = threadIdx.x;

    const float* Sp = S + (size_t)i * NL * MT + (size_t)b * NR;
    for (int idx = tid; idx < NR * NL; idx += 128) {
        int l = idx / NR, r = idx - l * NR;
        FS[r * 41 + l] = __ldcs(Sp + (size_t)l * MT + r);
    }
    for (int idx = tid; idx < NR * NR; idx += 128) Gs[idx] = g_G[(size_t)b * (NR * NR) + idx];
    for (int idx = tid; idx < NL * NL; idx += 128) Hs[idx] = g_H[(size_t)i * (NL * NL) + idx];
    if (tid < NR) Pb[tid] = g_P[(size_t)i * MT + b * NR + tid];
    else if (tid >= 64 && tid < 64 + NL) Qi[tid - 64] = g_Q[(size_t)b * NT + i * NL + (tid - 64)];
    __syncthreads();

    if (tid < NL) {                         // column norms over r -> lambda/cn
        int l = tid; float s = 0.f;
#pragma unroll
        for (int r = 0; r < NR; r++) { float v = FS[r * 41 + l]; s = fmaf(v, v, s); }
        cnl[l] = LAMS / (sqrtf(s) + EPSF);
    } else if (tid >= 64 && tid < 64 + NR) { // row norms over l -> lambda/rn
        int r = tid - 64; float s = 0.f;
#pragma unroll
        for (int l = 0; l < NL; l++) { float v = FS[r * 41 + l]; s = fmaf(v, v, s); }
        rnl[r] = LAMS / (sqrtf(s) + EPSF);
    }
    __syncthreads();

    for (int idx = tid; idx < NR * NL; idx += 128) {
        int l = idx / NR, r = idx - l * NR;
        float v = FS[r * 41 + l];
        Am[l * 44 + r] = __expf(v * rnl[r]);
        Cm[r * 44 + l] = __expf(v * cnl[l]);
    }
    __syncthreads();

    // fused mini-GEMM + quadratic form: 180 tasks, each a 4x4 tile
    for (int task = tid; task < 180; task += 128) {
        float4 acc0 = make_float4(0.f, 0.f, 0.f, 0.f);
        float4 acc1 = acc0, acc2 = acc0, acc3 = acc0;
        float4 st0 = acc0, st1 = acc0, st2 = acc0, st3 = acc0;
        if (task < 90) {
            int lg = task / 9, rg = task - lg * 9;
            const float* Ab = Am + lg * 4 * 44;
            const float* Gb = Gs + rg * 4;
#pragma unroll
            for (int rp4 = 0; rp4 < 9; rp4++) {
                float4 a0 = *(const float4*)(Ab + rp4 * 4);
                float4 a1 = *(const float4*)(Ab + 44 + rp4 * 4);
                float4 a2 = *(const float4*)(Ab + 88 + rp4 * 4);
                float4 a3 = *(const float4*)(Ab + 132 + rp4 * 4);
                if (rp4 == rg) { st0 = a0; st1 = a1; st2 = a2; st3 = a3; }
                float4 g0 = *(const float4*)(Gb + (rp4 * 4 + 0) * 36);
                float4 g1 = *(const float4*)(Gb + (rp4 * 4 + 1) * 36);
                float4 g2 = *(const float4*)(Gb + (rp4 * 4 + 2) * 36);
                float4 g3 = *(const float4*)(Gb + (rp4 * 4 + 3) * 36);
#define ACC4(ACC, AV)                                                          \
                ACC.x = fmaf(AV.x, g0.x, ACC.x); ACC.y = fmaf(AV.x, g0.y, ACC.y); \
                ACC.z = fmaf(AV.x, g0.z, ACC.z); ACC.w = fmaf(AV.x, g0.w, ACC.w); \
                ACC.x = fmaf(AV.y, g1.x, ACC.x); ACC.y = fmaf(AV.y, g1.y, ACC.y); \
                ACC.z = fmaf(AV.y, g1.z, ACC.z); ACC.w = fmaf(AV.y, g1.w, ACC.w); \
                ACC.x = fmaf(AV.z, g2.x, ACC.x); ACC.y = fmaf(AV.z, g2.y, ACC.y); \
                ACC.z = fmaf(AV.z, g2.z, ACC.z); ACC.w = fmaf(AV.z, g2.w, ACC.w); \
                ACC.x = fmaf(AV.w, g3.x, ACC.x); ACC.y = fmaf(AV.w, g3.y, ACC.y); \
                ACC.z = fmaf(AV.w, g3.z, ACC.z); ACC.w = fmaf(AV.w, g3.w, ACC.w);
                ACC4(acc0, a0) ACC4(acc1, a1) ACC4(acc2, a2) ACC4(acc3, a3)
            }
            int l = lg * 4;
            w2p1[(l + 0) * 9 + rg] = acc0.x * st0.x + acc0.y * st0.y + acc0.z * st0.z + acc0.w * st0.w;
            w2p1[(l + 1) * 9 + rg] = acc1.x * st1.x + acc1.y * st1.y + acc1.z * st1.z + acc1.w * st1.w;
            w2p1[(l + 2) * 9 + rg] = acc2.x * st2.x + acc2.y * st2.y + acc2.z * st2.z + acc2.w * st2.w;
            w2p1[(l + 3) * 9 + rg] = acc3.x * st3.x + acc3.y * st3.y + acc3.z * st3.z + acc3.w * st3.w;
        } else {
            int t2 = task - 90;
            int rg = t2 / 10, lg = t2 - rg * 10;
            const float* Cb = Cm + rg * 4 * 44;
            const float* Hb = Hs + lg * 4;
#pragma unroll
            for (int lp4 = 0; lp4 < 10; lp4++) {
                float4 a0 = *(const float4*)(Cb + lp4 * 4);
                float4 a1 = *(const float4*)(Cb + 44 + lp4 * 4);
                float4 a2 = *(const float4*)(Cb + 88 + lp4 * 4);
                float4 a3 = *(const float4*)(Cb + 132 + lp4 * 4);
                if (lp4 == lg) { st0 = a0; st1 = a1; st2 = a2; st3 = a3; }
                float4 g0 = *(const float4*)(Hb + (lp4 * 4 + 0) * 40);
                float4 g1 = *(const float4*)(Hb + (lp4 * 4 + 1) * 40);
                float4 g2 = *(const float4*)(Hb + (lp4 * 4 + 2) * 40);
                float4 g3 = *(const float4*)(Hb + (lp4 * 4 + 3) * 40);
                ACC4(acc0, a0) ACC4(acc1, a1) ACC4(acc2, a2) ACC4(acc3, a3)
#undef ACC4
            }
            int r = rg * 4;
            w2p2[(r + 0) * 10 + lg] = acc0.x * st0.x + acc0.y * st0.y + acc0.z * st0.z + acc0.w * st0.w;
            w2p2[(r + 1) * 10 + lg] = acc1.x * st1.x + acc1.y * st1.y + acc1.z * st1.z + acc1.w * st1.w;
            w2p2[(r + 2) * 10 + lg] = acc2.x * st2.x + acc2.y * st2.y + acc2.z * st2.z + acc2.w * st2.w;
            w2p2[(r + 3) * 10 + lg] = acc3.x * st3.x + acc3.y * st3.y + acc3.z * st3.z + acc3.w * st3.w;
        }
    }
    __syncthreads();

    if (tid < NL) {                          // t2i: word l
        int l = tid; float w12 = 0.f, w2 = 0.f;
#pragma unroll
        for (int r = 0; r < NR; r++) w12 = fmaf(Am[l * 44 + r], Pb[r], w12);
#pragma unroll
        for (int k = 0; k < 9; k++) w2 += w2p1[l * 9 + k];
        float den = fmaxf(g_w1t[i] * sqrtf(fmaxf(w2, 0.f)), EPSF);
        s1s[l] = __fdividef(w12, den);
    } else if (tid >= 64 && tid < 64 + NR) { // i2t: region r
        int r = tid - 64; float w12 = 0.f, w2 = 0.f;
#pragma unroll
        for (int l = 0; l < NL; l++) w12 = fmaf(Cm[r * 44 + l], Qi[l], w12);
#pragma unroll
        for (int k = 0; k < 10; k++) w2 += w2p2[r * 10 + k];
        float den = fmaxf(g_w1i[b] * sqrtf(fmaxf(w2, 0.f)), EPSF);
        s2s[r] = __fdividef(w12, den);
    }
    __syncthreads();

    if (tid == 0) {
        float m1 = 0.f, m2 = 0.f;
#pragma unroll
        for (int l = 0; l < NL; l++) m1 += s1s[l];
#pragma unroll
        for (int r = 0; r < NR; r++) m2 += s2s[r];
        out[(size_t)b * NB + i] = g_base[b * NB + i] + m1 * (1.f / NL) + m2 * (1.f / NR);
    }
}

// ============================ launch ============================
extern "C" void kernel_launch(void* const* d_in, const int* in_sizes, int n_in,
                              void* d_out, int out_size) {
    (void)in_sizes; (void)n_in; (void)out_size;
    const float* pool_img = (const float*)d_in[0];
    const float* img_emb  = (const float*)d_in[1];
    const float* pool_txt = (const float*)d_in[2];
    const float* cap_emb  = (const float*)d_in[3];
    float* out = (float*)d_out;

    cudaFuncSetAttribute((const void*)gram_kernel,
                         cudaFuncAttributeMaxDynamicSharedMemorySize, NL * ND * 4);
    cudaFuncSetAttribute((const void*)s_gemm,
                         cudaFuncAttributeMaxDynamicSharedMemorySize, GEMM_SMEM);
    cudaFuncSetAttribute((const void*)pair_epilogue,
                         cudaFuncAttributeMaxDynamicSharedMemorySize, EPI_SMEM);

    float* dS = nullptr;
    cudaGetSymbolAddress((void**)&dS, g_S);
    __nv_bfloat16* dAh = nullptr; cudaGetSymbolAddress((void**)&dAh, g_Ah);
    __nv_bfloat16* dBh = nullptr; cudaGetSymbolAddress((void**)&dBh, g_Bh);

    // order: s_gemm stays at launch index 3 (profiled slot)
    cvt_kernel<<<9984, 256>>>(img_emb, pool_img, cap_emb, pool_txt);
    gram_kernel<<<NB, 256, NR * ND * 4>>>(img_emb, NR, 0);
    gram_kernel<<<NB, 256, NL * ND * 4>>>(cap_emb, NL, 1);
    s_gemm<<<dim3(82, 74), 256, GEMM_SMEM>>>(dAh, dBh, dS);
    norm_kernel<<<64, 256>>>(pool_img, pool_txt);
    sgemm_tn<<<dim3(NB / 64, NB / 64), 256>>>(pool_img, pool_txt, NB, NB, ND);
    pair_epilogue<<<dim3(NB, NB), 128, EPI_SMEM>>>(dS, out);
}

// round 12
// speedup vs baseline: 1.3782x; 1.0028x over previous
#include <cuda_runtime.h>
#include <cuda_bf16.h>
#include <math.h>
#include <cstdint>

#define NB 256
#define NR 36
#define NL 40
#define ND 1024
#define MT (NB * NR)   /* 9216  */
#define NT (NB * NL)   /* 10240 */
#define EPSF 1e-8f
#define LAMS 9.0f

#define MROWS 9472     /* 9216 img rows + 256 pool_img */
#define NROWS 10496    /* 10240 cap rows + 256 pool_txt */

// ---- scratch (device globals; no allocation allowed) ----
__device__ float g_S[(size_t)MT * NT];           // S^T[n][m], leaky-relu'd (378MB)
__device__ __nv_bfloat16 g_Ah[(size_t)MROWS * ND];  // bf16 img_emb ++ pool_img
__device__ __nv_bfloat16 g_Bh[(size_t)NROWS * ND];  // bf16 cap_emb ++ pool_txt
__device__ float g_P[NB * NB * NR];
__device__ float g_Q[NB * NB * NL];
__device__ float g_G[NB * NR * NR];
__device__ float g_H[NB * NL * NL];
__device__ float g_base[NB * NB];
__device__ float g_w1i[NB];
__device__ float g_w1t[NB];

__device__ __forceinline__ float4 ldg4(const float* p) {
    return *reinterpret_cast<const float4*>(p);
}
__device__ __forceinline__ uint32_t pack_bf2(float x, float y) {
    __nv_bfloat162 h = __float22bfloat162_rn(make_float2(x, y));
    return *reinterpret_cast<uint32_t*>(&h);
}
__device__ __forceinline__ void mma_bf16(float* c, const uint32_t* a, const uint32_t* b) {
    asm volatile(
        "mma.sync.aligned.m16n8k16.row.col.f32.bf16.bf16.f32 "
        "{%0,%1,%2,%3}, {%4,%5,%6,%7}, {%8,%9}, {%0,%1,%2,%3};"
        : "+f"(c[0]), "+f"(c[1]), "+f"(c[2]), "+f"(c[3])
        : "r"(a[0]), "r"(a[1]), "r"(a[2]), "r"(a[3]), "r"(b[0]), "r"(b[1]));
}
__device__ __forceinline__ void cpa16(uint32_t saddr, const void* gaddr) {
    asm volatile("cp.async.ca.shared.global [%0], [%1], 16;"
                 :: "r"(saddr), "l"(gaddr) : "memory");
}
__device__ __forceinline__ void ldsm_x4(uint32_t& r0, uint32_t& r1, uint32_t& r2,
                                        uint32_t& r3, uint32_t addr) {
    asm volatile("ldmatrix.sync.aligned.m8n8.x4.shared.b16 {%0,%1,%2,%3}, [%4];"
                 : "=r"(r0), "=r"(r1), "=r"(r2), "=r"(r3) : "r"(addr));
}

// ============================ bf16 conversion (augmented operands) ============================
__global__ void cvt_kernel(const float* __restrict__ img, const float* __restrict__ pimg,
                           const float* __restrict__ cap, const float* __restrict__ ptxt) {
    size_t g8 = (size_t)blockIdx.x * 256 + threadIdx.x;
    const size_t A8 = (size_t)MROWS * (ND / 8);
    const float* src;
    uint32_t* dst;
    if (g8 < A8) {
        size_t off = g8 * 8;
        size_t row = off >> 10, col = off & 1023;
        src = (row < 9216) ? (img + row * ND + col) : (pimg + (row - 9216) * ND + col);
        dst = reinterpret_cast<uint32_t*>(g_Ah) + g8 * 4;
    } else {
        size_t h8 = g8 - A8;
        size_t off = h8 * 8;
        size_t row = off >> 10, col = off & 1023;
        src = (row < 10240) ? (cap + row * ND + col) : (ptxt + (row - 10240) * ND + col);
        dst = reinterpret_cast<uint32_t*>(g_Bh) + h8 * 4;
    }
    float4 x = ldg4(src), y = ldg4(src + 4);
    *reinterpret_cast<uint4*>(dst) =
        make_uint4(pack_bf2(x.x, x.y), pack_bf2(x.z, x.w),
                   pack_bf2(y.x, y.y), pack_bf2(y.z, y.w));
}

// ============================ precompute kernels ============================
__global__ void norm_kernel(const float* __restrict__ pi, const float* __restrict__ pt) {
    int w = blockIdx.x * 8 + (threadIdx.x >> 5);
    int lane = threadIdx.x & 31;
    const float* src = (w < NB) ? (pi + (size_t)w * ND) : (pt + (size_t)(w - NB) * ND);
    float s = 0.f;
    for (int j = lane; j < ND; j += 32) { float v = src[j]; s = fmaf(v, v, s); }
#pragma unroll
    for (int o = 16; o; o >>= 1) s += __shfl_down_sync(0xffffffffu, s, o);
    if (lane == 0) {
        float r = sqrtf(s);
        if (w < NB) g_w1i[w] = r; else g_w1t[w - NB] = r;
    }
}

__global__ void sgemm_tn(const float* __restrict__ A, const float* __restrict__ Bm,
                         int M, int N, int K) {
    float* C = g_base;
    __shared__ float As[16 * 64];
    __shared__ float Bs[16 * 64];
    int tid = threadIdx.x;
    int tx = tid & 15, ty = tid >> 4;
    int m0 = blockIdx.y * 64, n0 = blockIdx.x * 64;
    int row = tid >> 2, q = tid & 3;
    float acc[4][4] = {};
    for (int k0 = 0; k0 < K; k0 += 16) {
        float4 a = ldg4(A + (size_t)(m0 + row) * K + k0 + q * 4);
        float4 bb = ldg4(Bm + (size_t)(n0 + row) * K + k0 + q * 4);
        As[(q * 4 + 0) * 64 + row] = a.x;  As[(q * 4 + 1) * 64 + row] = a.y;
        As[(q * 4 + 2) * 64 + row] = a.z;  As[(q * 4 + 3) * 64 + row] = a.w;
        Bs[(q * 4 + 0) * 64 + row] = bb.x; Bs[(q * 4 + 1) * 64 + row] = bb.y;
        Bs[(q * 4 + 2) * 64 + row] = bb.z; Bs[(q * 4 + 3) * 64 + row] = bb.w;
        __syncthreads();
#pragma unroll
        for (int k = 0; k < 16; k++) {
            float4 av = *(const float4*)(As + k * 64 + ty * 4);
            float4 bv = *(const float4*)(Bs + k * 64 + tx * 4);
            float aa[4] = {av.x, av.y, av.z, av.w};
            float bw[4] = {bv.x, bv.y, bv.z, bv.w};
#pragma unroll
            for (int ii = 0; ii < 4; ii++)
#pragma unroll
                for (int jj = 0; jj < 4; jj++)
                    acc[ii][jj] = fmaf(aa[ii], bw[jj], acc[ii][jj]);
        }
        __syncthreads();
    }
#pragma unroll
    for (int ii = 0; ii < 4; ii++)
#pragma unroll
        for (int jj = 0; jj < 4; jj++)
            C[(size_t)(m0 + ty * 4 + ii) * N + n0 + tx * 4 + jj] = acc[ii][jj];
}

// per-row Gram, 4x4 register-blocked, symmetric
__global__ void gram_kernel(const float* __restrict__ emb, int ROWS, int which) {
    extern __shared__ float Es[];
    float* out = which ? g_H : g_G;
    int b = blockIdx.x, tid = threadIdx.x;
    int wid = tid >> 5, lane = tid & 31;
    int n = ROWS * ND;
    int np = ROWS * ROWS;
    for (int idx = tid; idx < n; idx += 256) Es[idx] = emb[(size_t)b * n + idx];
    __syncthreads();
    int nt4 = ROWS / 4;
    int count = nt4 * (nt4 + 1) / 2;
    for (int p = wid; p < count; p += 8) {
        int pl = p, tr = 0;
        while (pl >= nt4 - tr) { pl -= nt4 - tr; tr++; }
        int tc = tr + pl;
        const float* E1 = Es + (size_t)tr * 4 * ND;
        const float* E2 = Es + (size_t)tc * 4 * ND;
        float acc[4][4] = {};
        for (int kk = 0; kk < ND; kk += 32) {
            int k = kk + lane;
            float e1[4], e2[4];
#pragma unroll
            for (int j = 0; j < 4; j++) { e1[j] = E1[j * ND + k]; e2[j] = E2[j * ND + k]; }
#pragma unroll
            for (int j = 0; j < 4; j++)
#pragma unroll
                for (int jj = 0; jj < 4; jj++)
                    acc[j][jj] = fmaf(e1[j], e2[jj], acc[j][jj]);
        }
#pragma unroll
        for (int j = 0; j < 4; j++)
#pragma unroll
            for (int jj = 0; jj < 4; jj++) {
#pragma unroll
                for (int o = 16; o; o >>= 1)
                    acc[j][jj] += __shfl_xor_sync(0xffffffffu, acc[j][jj], o);
            }
        if (lane == 0) {
#pragma unroll
            for (int j = 0; j < 4; j++)
#pragma unroll
                for (int jj = 0; jj < 4; jj++) {
                    float v = acc[j][jj];
                    out[(size_t)b * np + (tr * 4 + j) * ROWS + tc * 4 + jj] = v;
                    out[(size_t)b * np + (tc * 4 + jj) * ROWS + tr * 4 + j] = v;
                }
        }
    }
}

// ============================ bf16 cp.async pipelined GEMM (R9 proven config) ============================
#define BM 128
#define BN 256
#define BK 32
#define ASZW (BM * 20)
#define STGW (ASZW + BN * 20)
#define STAGES 4
#define GEMM_SMEM (STAGES * STGW * 4)

__global__ void __launch_bounds__(256, 1) s_gemm(const __nv_bfloat16* __restrict__ Ah,
                                                 const __nv_bfloat16* __restrict__ Bh,
                                                 float* __restrict__ S) {
    extern __shared__ uint32_t smw[];
    uint32_t sb;
    asm("{ .reg .u64 t; cvta.to.shared.u64 t, %1; cvt.u32.u64 %0, t; }" : "=r"(sb) : "l"(smw));
    const int tid = threadIdx.x;
    const int wid = tid >> 5;
    const int lane = tid & 31;
    const int g = lane >> 2;
    const int t = lane & 3;
    const int wm = wid >> 2;
    const int wn = wid & 3;
    const int by = blockIdx.y;
    const int bx = blockIdx.x;
    const int m0 = by * BM;
    const int n0 = bx * BN;
    const bool pBlk = (bx == 40);
    const bool qBlk = (by >= 72);

    const int arow = tid >> 2;
    const int ac = tid & 3;
    const __nv_bfloat16* Agp = (qBlk ? (Ah + (size_t)9216 * ND + (size_t)(by - 72) * BM * ND)
                                     : (Ah + (size_t)m0 * ND)) + (size_t)arow * ND + ac * 8;
    const __nv_bfloat16* Bgp = (pBlk ? (Bh + (size_t)10240 * ND)
                                     : (Bh + (size_t)n0 * ND)) + (size_t)arow * ND + ac * 8;
    const uint32_t sA = sb + (uint32_t)(arow * 20 + ac * 4) * 4;
    const uint32_t sB = sb + (uint32_t)(ASZW + arow * 20 + ac * 4) * 4;

    // ldmatrix lane geometry
    const int alr = (lane & 7) + ((lane >> 3) & 1) * 8;
    const int ahf = (lane >> 4) & 1;
    const int blr = (lane & 7) + ((lane >> 4) & 1) * 8;
    const int bhf = (lane >> 3) & 1;
    const uint32_t aFrag = sb + (uint32_t)(((wm * 64 + alr) * 20) + ahf * 4) * 4;
    const uint32_t bFrag = sb + (uint32_t)((ASZW + (wn * 64 + blr) * 20) + bhf * 4) * 4;

    float cacc[4][8][4];
#pragma unroll
    for (int a = 0; a < 4; a++)
#pragma unroll
        for (int bb = 0; bb < 8; bb++)
#pragma unroll
            for (int cc = 0; cc < 4; cc++) cacc[a][bb][cc] = 0.f;

#define ISSUE(stg, kc) do {                                                    \
    uint32_t so = (uint32_t)(stg) * (STGW * 4);                                \
    _Pragma("unroll")                                                          \
    for (int j = 0; j < 2; j++)                                                \
        cpa16(sA + so + j * (64 * 20 * 4), Agp + (size_t)j * 64 * ND + (kc));  \
    _Pragma("unroll")                                                          \
    for (int j = 0; j < 4; j++)                                                \
        cpa16(sB + so + j * (64 * 20 * 4), Bgp + (size_t)j * 64 * ND + (kc));  \
} while (0)

#define COMPUTE(stg, ks) do {                                                  \
    const uint32_t so = (uint32_t)(stg) * (STGW * 4) + (ks) * 32;              \
    uint32_t af[4][4];                                                         \
    uint32_t bf[8][2];                                                         \
    _Pragma("unroll")                                                          \
    for (int mt = 0; mt < 4; mt++)                                             \
        ldsm_x4(af[mt][0], af[mt][1], af[mt][2], af[mt][3],                    \
                aFrag + so + mt * (16 * 20 * 4));                              \
    _Pragma("unroll")                                                          \
    for (int np = 0; np < 4; np++)                                             \
        ldsm_x4(bf[2 * np][0], bf[2 * np][1], bf[2 * np + 1][0],               \
                bf[2 * np + 1][1], bFrag + so + np * (16 * 20 * 4));           \
    _Pragma("unroll")                                                          \
    for (int mt = 0; mt < 4; mt++)                                             \
        _Pragma("unroll")                                                      \
        for (int nt = 0; nt < 8; nt++)                                         \
            mma_bf16(cacc[mt][nt], af[mt], bf[nt]);                            \
} while (0)

    ISSUE(0, 0);  asm volatile("cp.async.commit_group;" ::: "memory");
    ISSUE(1, 32); asm volatile("cp.async.commit_group;" ::: "memory");
    ISSUE(2, 64); asm volatile("cp.async.commit_group;" ::: "memory");

#pragma unroll 1
    for (int c = 0; c < 32; c++) {
        asm volatile("cp.async.wait_group 2;" ::: "memory");
        __syncthreads();
        COMPUTE(c & 3, 0);
        COMPUTE(c & 3, 1);
        if (c < 29) ISSUE((c + 3) & 3, (c + 3) * BK);
        asm volatile("cp.async.commit_group;" ::: "memory");
    }

    if (pBlk && qBlk) return;

    if (!pBlk && !qBlk) {
#pragma unroll
        for (int mt = 0; mt < 4; mt++) {
            int m = m0 + wm * 64 + mt * 16 + g;
#pragma unroll
            for (int nt = 0; nt < 8; nt++) {
                int n = n0 + wn * 64 + nt * 8 + 2 * t;
                float v0 = cacc[mt][nt][0]; v0 = (v0 >= 0.f) ? v0 : 0.1f * v0;
                float v1 = cacc[mt][nt][1]; v1 = (v1 >= 0.f) ? v1 : 0.1f * v1;
                float v2 = cacc[mt][nt][2]; v2 = (v2 >= 0.f) ? v2 : 0.1f * v2;
                float v3 = cacc[mt][nt][3]; v3 = (v3 >= 0.f) ? v3 : 0.1f * v3;
                __stcs(S + (size_t)n * MT + m, v0);
                __stcs(S + (size_t)(n + 1) * MT + m, v1);
                __stcs(S + (size_t)n * MT + m + 8, v2);
                __stcs(S + (size_t)(n + 1) * MT + m + 8, v3);
            }
        }
    } else if (pBlk) {
#pragma unroll
        for (int mt = 0; mt < 4; mt++) {
            int m = m0 + wm * 64 + mt * 16 + g;
#pragma unroll
            for (int nt = 0; nt < 8; nt++) {
                int i = wn * 64 + nt * 8 + 2 * t;
                __stcs(g_P + (size_t)i * MT + m, cacc[mt][nt][0]);
                __stcs(g_P + (size_t)(i + 1) * MT + m, cacc[mt][nt][1]);
                __stcs(g_P + (size_t)i * MT + m + 8, cacc[mt][nt][2]);
                __stcs(g_P + (size_t)(i + 1) * MT + m + 8, cacc[mt][nt][3]);
            }
        }
    } else {
#pragma unroll
        for (int mt = 0; mt < 4; mt++) {
            int b = (by - 72) * BM + wm * 64 + mt * 16 + g;
#pragma unroll
            for (int nt = 0; nt < 8; nt++) {
                int n = n0 + wn * 64 + nt * 8 + 2 * t;
                __stcs(g_Q + (size_t)b * NT + n, cacc[mt][nt][0]);
                __stcs(g_Q + (size_t)b * NT + n + 1, cacc[mt][nt][1]);
                __stcs(g_Q + (size_t)(b + 8) * NT + n, cacc[mt][nt][2]);
                __stcs(g_Q + (size_t)(b + 8) * NT + n + 1, cacc[mt][nt][3]);
            }
        }
    }
#undef ISSUE
#undef COMPUTE
}

// ============================ per-pair epilogue: R7 body, 2 pairs per block ============================
// per-half layout (7264 words): FS 0 (1600, stride 41) | Am 1600 (40x44) | Cm 3360 (36x44)
//   Hs 4944 (40x40) | w2p1 6544 (40x9) | w2p2 6904 (36x10)
// shared Gs @ 14528 (36x36). total 15824 words = 63296 B
#define HSZ 7264
#define EPI_SMEM ((2 * HSZ + 1296) * 4)

__global__ void __launch_bounds__(256) pair_epilogue(const float* __restrict__ S,
                                                     float* __restrict__ out) {
    extern __shared__ float sh[];
    __shared__ float Pb[2][NR], Qi[2][NL], rnl[2][NR], cnl[2][NL], s1s[2][NL], s2s[2][NR];
    const int tid = threadIdx.x;
    const int h = tid >> 7;
    const int tt = tid & 127;
    const int i = blockIdx.x * 2 + h;
    const int b = blockIdx.y;

    float* hb = sh + h * HSZ;
    float* FS = hb;
    float* Am = hb + 1600;
    float* Cm = hb + 3360;
    float* Hs = hb + 4944;
    float* w2p1 = hb + 6544;
    float* w2p2 = hb + 6904;
    float* Gs = sh + 2 * HSZ;

    const float* Sp = S + (size_t)i * NL * MT + (size_t)b * NR;
    for (int idx = tt; idx < NR * NL; idx += 128) {
        int l = idx / NR, r = idx - l * NR;
        FS[r * 41 + l] = __ldcs(Sp + (size_t)l * MT + r);
    }
    for (int idx = tid; idx < NR * NR; idx += 256) Gs[idx] = g_G[(size_t)b * (NR * NR) + idx];
    for (int idx = tt; idx < NL * NL; idx += 128) Hs[idx] = g_H[(size_t)i * (NL * NL) + idx];
    if (tt < NR) Pb[h][tt] = g_P[(size_t)i * MT + b * NR + tt];
    else if (tt >= 64 && tt < 64 + NL) Qi[h][tt - 64] = g_Q[(size_t)b * NT + i * NL + (tt - 64)];
    __syncthreads();

    if (tt < NL) {                          // column norms over r -> lambda/cn
        int l = tt; float s = 0.f;
#pragma unroll
        for (int r = 0; r < NR; r++) { float v = FS[r * 41 + l]; s = fmaf(v, v, s); }
        cnl[h][l] = LAMS / (sqrtf(s) + EPSF);
    } else if (tt >= 64 && tt < 64 + NR) {  // row norms over l -> lambda/rn
        int r = tt - 64; float s = 0.f;
#pragma unroll
        for (int l = 0; l < NL; l++) { float v = FS[r * 41 + l]; s = fmaf(v, v, s); }
        rnl[h][r] = LAMS / (sqrtf(s) + EPSF);
    }
    __syncthreads();

    for (int idx = tt; idx < NR * NL; idx += 128) {
        int l = idx / NR, r = idx - l * NR;
        float v = FS[r * 41 + l];
        Am[l * 44 + r] = __expf(v * rnl[h][r]);
        Cm[r * 44 + l] = __expf(v * cnl[h][l]);
    }
    __syncthreads();

    // fused mini-GEMM + quadratic form: 180 tasks per half, each a 4x4 tile
    for (int task = tt; task < 180; task += 128) {
        float4 acc0 = make_float4(0.f, 0.f, 0.f, 0.f);
        float4 acc1 = acc0, acc2 = acc0, acc3 = acc0;
        float4 st0 = acc0, st1 = acc0, st2 = acc0, st3 = acc0;
        if (task < 90) {
            int lg = task / 9, rg = task - lg * 9;
            const float* Ab = Am + lg * 4 * 44;
            const float* Gb = Gs + rg * 4;
#pragma unroll
            for (int rp4 = 0; rp4 < 9; rp4++) {
                float4 a0 = *(const float4*)(Ab + rp4 * 4);
                float4 a1 = *(const float4*)(Ab + 44 + rp4 * 4);
                float4 a2 = *(const float4*)(Ab + 88 + rp4 * 4);
                float4 a3 = *(const float4*)(Ab + 132 + rp4 * 4);
                if (rp4 == rg) { st0 = a0; st1 = a1; st2 = a2; st3 = a3; }
                float4 g0 = *(const float4*)(Gb + (rp4 * 4 + 0) * 36);
                float4 g1 = *(const float4*)(Gb + (rp4 * 4 + 1) * 36);
                float4 g2 = *(const float4*)(Gb + (rp4 * 4 + 2) * 36);
                float4 g3 = *(const float4*)(Gb + (rp4 * 4 + 3) * 36);
#define ACC4(ACC, AV)                                                          \
                ACC.x = fmaf(AV.x, g0.x, ACC.x); ACC.y = fmaf(AV.x, g0.y, ACC.y); \
                ACC.z = fmaf(AV.x, g0.z, ACC.z); ACC.w = fmaf(AV.x, g0.w, ACC.w); \
                ACC.x = fmaf(AV.y, g1.x, ACC.x); ACC.y = fmaf(AV.y, g1.y, ACC.y); \
                ACC.z = fmaf(AV.y, g1.z, ACC.z); ACC.w = fmaf(AV.y, g1.w, ACC.w); \
                ACC.x = fmaf(AV.z, g2.x, ACC.x); ACC.y = fmaf(AV.z, g2.y, ACC.y); \
                ACC.z = fmaf(AV.z, g2.z, ACC.z); ACC.w = fmaf(AV.z, g2.w, ACC.w); \
                ACC.x = fmaf(AV.w, g3.x, ACC.x); ACC.y = fmaf(AV.w, g3.y, ACC.y); \
                ACC.z = fmaf(AV.w, g3.z, ACC.z); ACC.w = fmaf(AV.w, g3.w, ACC.w);
                ACC4(acc0, a0) ACC4(acc1, a1) ACC4(acc2, a2) ACC4(acc3, a3)
            }
            int l = lg * 4;
            w2p1[(l + 0) * 9 + rg] = acc0.x * st0.x + acc0.y * st0.y + acc0.z * st0.z + acc0.w * st0.w;
            w2p1[(l + 1) * 9 + rg] = acc1.x * st1.x + acc1.y * st1.y + acc1.z * st1.z + acc1.w * st1.w;
            w2p1[(l + 2) * 9 + rg] = acc2.x * st2.x + acc2.y * st2.y + acc2.z * st2.z + acc2.w * st2.w;
            w2p1[(l + 3) * 9 + rg] = acc3.x * st3.x + acc3.y * st3.y + acc3.z * st3.z + acc3.w * st3.w;
        } else {
            int t2 = task - 90;
            int rg = t2 / 10, lg = t2 - rg * 10;
            const float* Cb = Cm + rg * 4 * 44;
            const float* Hb = Hs + lg * 4;
#pragma unroll
            for (int lp4 = 0; lp4 < 10; lp4++) {
                float4 a0 = *(const float4*)(Cb + lp4 * 4);
                float4 a1 = *(const float4*)(Cb + 44 + lp4 * 4);
                float4 a2 = *(const float4*)(Cb + 88 + lp4 * 4);
                float4 a3 = *(const float4*)(Cb + 132 + lp4 * 4);
                if (lp4 == lg) { st0 = a0; st1 = a1; st2 = a2; st3 = a3; }
                float4 g0 = *(const float4*)(Hb + (lp4 * 4 + 0) * 40);
                float4 g1 = *(const float4*)(Hb + (lp4 * 4 + 1) * 40);
                float4 g2 = *(const float4*)(Hb + (lp4 * 4 + 2) * 40);
                float4 g3 = *(const float4*)(Hb + (lp4 * 4 + 3) * 40);
                ACC4(acc0, a0) ACC4(acc1, a1) ACC4(acc2, a2) ACC4(acc3, a3)
#undef ACC4
            }
            int r = rg * 4;
            w2p2[(r + 0) * 10 + lg] = acc0.x * st0.x + acc0.y * st0.y + acc0.z * st0.z + acc0.w * st0.w;
            w2p2[(r + 1) * 10 + lg] = acc1.x * st1.x + acc1.y * st1.y + acc1.z * st1.z + acc1.w * st1.w;
            w2p2[(r + 2) * 10 + lg] = acc2.x * st2.x + acc2.y * st2.y + acc2.z * st2.z + acc2.w * st2.w;
            w2p2[(r + 3) * 10 + lg] = acc3.x * st3.x + acc3.y * st3.y + acc3.z * st3.z + acc3.w * st3.w;
        }
    }
    __syncthreads();

    if (tt < NL) {                           // t2i: word l
        int l = tt; float w12 = 0.f, w2 = 0.f;
#pragma unroll
        for (int r = 0; r < NR; r++) w12 = fmaf(Am[l * 44 + r], Pb[h][r], w12);
#pragma unroll
        for (int k = 0; k < 9; k++) w2 += w2p1[l * 9 + k];
        float den = fmaxf(g_w1t[i] * sqrtf(fmaxf(w2, 0.f)), EPSF);
        s1s[h][l] = __fdividef(w12, den);
    } else if (tt >= 64 && tt < 64 + NR) {   // i2t: region r
        int r = tt - 64; float w12 = 0.f, w2 = 0.f;
#pragma unroll
        for (int l = 0; l < NL; l++) w12 = fmaf(Cm[r * 44 + l], Qi[h][l], w12);
#pragma unroll
        for (int k = 0; k < 10; k++) w2 += w2p2[r * 10 + k];
        float den = fmaxf(g_w1i[b] * sqrtf(fmaxf(w2, 0.f)), EPSF);
        s2s[h][r] = __fdividef(w12, den);
    }
    __syncthreads();

    if (tt == 0) {
        float m1 = 0.f, m2 = 0.f;
#pragma unroll
        for (int l = 0; l < NL; l++) m1 += s1s[h][l];
#pragma unroll
        for (int r = 0; r < NR; r++) m2 += s2s[h][r];
        out[(size_t)b * NB + i] = g_base[b * NB + i] + m1 * (1.f / NL) + m2 * (1.f / NR);
    }
}

// ============================ launch ============================
extern "C" void kernel_launch(void* const* d_in, const int* in_sizes, int n_in,
                              void* d_out, int out_size) {
    (void)in_sizes; (void)n_in; (void)out_size;
    const float* pool_img = (const float*)d_in[0];
    const float* img_emb  = (const float*)d_in[1];
    const float* pool_txt = (const float*)d_in[2];
    const float* cap_emb  = (const float*)d_in[3];
    float* out = (float*)d_out;

    cudaFuncSetAttribute((const void*)gram_kernel,
                         cudaFuncAttributeMaxDynamicSharedMemorySize, NL * ND * 4);
    cudaFuncSetAttribute((const void*)s_gemm,
                         cudaFuncAttributeMaxDynamicSharedMemorySize, GEMM_SMEM);
    cudaFuncSetAttribute((const void*)pair_epilogue,
                         cudaFuncAttributeMaxDynamicSharedMemorySize, EPI_SMEM);

    float* dS = nullptr;
    cudaGetSymbolAddress((void**)&dS, g_S);
    __nv_bfloat16* dAh = nullptr; cudaGetSymbolAddress((void**)&dAh, g_Ah);
    __nv_bfloat16* dBh = nullptr; cudaGetSymbolAddress((void**)&dBh, g_Bh);

    // order: s_gemm stays at launch index 3 (profiled slot)
    cvt_kernel<<<9984, 256>>>(img_emb, pool_img, cap_emb, pool_txt);
    gram_kernel<<<NB, 256, NR * ND * 4>>>(img_emb, NR, 0);
    gram_kernel<<<NB, 256, NL * ND * 4>>>(cap_emb, NL, 1);
    s_gemm<<<dim3(41, 74), 256, GEMM_SMEM>>>(dAh, dBh, dS);
    norm_kernel<<<64, 256>>>(pool_img, pool_txt);
    sgemm_tn<<<dim3(NB / 64, NB / 64), 256>>>(pool_img, pool_txt, NB, NB, ND);
    pair_epilogue<<<dim3(NB / 2, NB), 256, EPI_SMEM>>>(dS, out);
}

// round 13
// speedup vs baseline: 1.6662x; 1.2090x over previous
#include <cuda_runtime.h>
#include <cuda_bf16.h>
#include <math.h>
#include <cstdint>

#define NB 256
#define NR 36
#define NL 40
#define ND 1024
#define MT (NB * NR)   /* 9216  */
#define NT (NB * NL)   /* 10240 */
#define EPSF 1e-8f
#define LAMS 9.0f

#define MROWS 9472     /* 9216 img rows + 256 pool_img */
#define NROWS 10496    /* 10240 cap rows + 256 pool_txt */

// ---- scratch (device globals; no allocation allowed) ----
__device__ float g_S[(size_t)MT * NT];           // S^T[n][m], leaky-relu'd (378MB)
__device__ __nv_bfloat16 g_Ah[(size_t)MROWS * ND];  // bf16 img_emb ++ pool_img
__device__ __nv_bfloat16 g_Bh[(size_t)NROWS * ND];  // bf16 cap_emb ++ pool_txt
__device__ float g_P[NB * NB * NR];
__device__ float g_Q[NB * NB * NL];
__device__ float g_G[NB * NR * NR];
__device__ float g_H[NB * NL * NL];
__device__ float g_base[NB * NB];
__device__ float g_w1i[NB];
__device__ float g_w1t[NB];

__device__ __forceinline__ float4 ldg4(const float* p) {
    return *reinterpret_cast<const float4*>(p);
}
__device__ __forceinline__ uint32_t pack_bf2(float x, float y) {
    __nv_bfloat162 h = __float22bfloat162_rn(make_float2(x, y));
    return *reinterpret_cast<uint32_t*>(&h);
}
__device__ __forceinline__ void mma_bf16(float* c, const uint32_t* a, const uint32_t* b) {
    asm volatile(
        "mma.sync.aligned.m16n8k16.row.col.f32.bf16.bf16.f32 "
        "{%0,%1,%2,%3}, {%4,%5,%6,%7}, {%8,%9}, {%0,%1,%2,%3};"
        : "+f"(c[0]), "+f"(c[1]), "+f"(c[2]), "+f"(c[3])
        : "r"(a[0]), "r"(a[1]), "r"(a[2]), "r"(a[3]), "r"(b[0]), "r"(b[1]));
}
__device__ __forceinline__ void cpa16(uint32_t saddr, const void* gaddr) {
    asm volatile("cp.async.ca.shared.global [%0], [%1], 16;"
                 :: "r"(saddr), "l"(gaddr) : "memory");
}
__device__ __forceinline__ void ldsm_x4(uint32_t& r0, uint32_t& r1, uint32_t& r2,
                                        uint32_t& r3, uint32_t addr) {
    asm volatile("ldmatrix.sync.aligned.m8n8.x4.shared.b16 {%0,%1,%2,%3}, [%4];"
                 : "=r"(r0), "=r"(r1), "=r"(r2), "=r"(r3) : "r"(addr));
}

// ============================ bf16 conversion (augmented operands) ============================
__global__ void cvt_kernel(const float* __restrict__ img, const float* __restrict__ pimg,
                           const float* __restrict__ cap, const float* __restrict__ ptxt) {
    size_t g8 = (size_t)blockIdx.x * 256 + threadIdx.x;
    const size_t A8 = (size_t)MROWS * (ND / 8);
    const float* src;
    uint32_t* dst;
    if (g8 < A8) {
        size_t off = g8 * 8;
        size_t row = off >> 10, col = off & 1023;
        src = (row < 9216) ? (img + row * ND + col) : (pimg + (row - 9216) * ND + col);
        dst = reinterpret_cast<uint32_t*>(g_Ah) + g8 * 4;
    } else {
        size_t h8 = g8 - A8;
        size_t off = h8 * 8;
        size_t row = off >> 10, col = off & 1023;
        src = (row < 10240) ? (cap + row * ND + col) : (ptxt + (row - 10240) * ND + col);
        dst = reinterpret_cast<uint32_t*>(g_Bh) + h8 * 4;
    }
    float4 x = ldg4(src), y = ldg4(src + 4);
    *reinterpret_cast<uint4*>(dst) =
        make_uint4(pack_bf2(x.x, x.y), pack_bf2(x.z, x.w),
                   pack_bf2(y.x, y.y), pack_bf2(y.z, y.w));
}

// ============================ precompute kernels ============================
__global__ void norm_kernel(const float* __restrict__ pi, const float* __restrict__ pt) {
    int w = blockIdx.x * 8 + (threadIdx.x >> 5);
    int lane = threadIdx.x & 31;
    const float* src = (w < NB) ? (pi + (size_t)w * ND) : (pt + (size_t)(w - NB) * ND);
    float s = 0.f;
    for (int j = lane; j < ND; j += 32) { float v = src[j]; s = fmaf(v, v, s); }
#pragma unroll
    for (int o = 16; o; o >>= 1) s += __shfl_down_sync(0xffffffffu, s, o);
    if (lane == 0) {
        float r = sqrtf(s);
        if (w < NB) g_w1i[w] = r; else g_w1t[w - NB] = r;
    }
}

__global__ void sgemm_tn(const float* __restrict__ A, const float* __restrict__ Bm,
                         int M, int N, int K) {
    float* C = g_base;
    __shared__ float As[16 * 64];
    __shared__ float Bs[16 * 64];
    int tid = threadIdx.x;
    int tx = tid & 15, ty = tid >> 4;
    int m0 = blockIdx.y * 64, n0 = blockIdx.x * 64;
    int row = tid >> 2, q = tid & 3;
    float acc[4][4] = {};
    for (int k0 = 0; k0 < K; k0 += 16) {
        float4 a = ldg4(A + (size_t)(m0 + row) * K + k0 + q * 4);
        float4 bb = ldg4(Bm + (size_t)(n0 + row) * K + k0 + q * 4);
        As[(q * 4 + 0) * 64 + row] = a.x;  As[(q * 4 + 1) * 64 + row] = a.y;
        As[(q * 4 + 2) * 64 + row] = a.z;  As[(q * 4 + 3) * 64 + row] = a.w;
        Bs[(q * 4 + 0) * 64 + row] = bb.x; Bs[(q * 4 + 1) * 64 + row] = bb.y;
        Bs[(q * 4 + 2) * 64 + row] = bb.z; Bs[(q * 4 + 3) * 64 + row] = bb.w;
        __syncthreads();
#pragma unroll
        for (int k = 0; k < 16; k++) {
            float4 av = *(const float4*)(As + k * 64 + ty * 4);
            float4 bv = *(const float4*)(Bs + k * 64 + tx * 4);
            float aa[4] = {av.x, av.y, av.z, av.w};
            float bw[4] = {bv.x, bv.y, bv.z, bv.w};
#pragma unroll
            for (int ii = 0; ii < 4; ii++)
#pragma unroll
                for (int jj = 0; jj < 4; jj++)
                    acc[ii][jj] = fmaf(aa[ii], bw[jj], acc[ii][jj]);
        }
        __syncthreads();
    }
#pragma unroll
    for (int ii = 0; ii < 4; ii++)
#pragma unroll
        for (int jj = 0; jj < 4; jj++)
            C[(size_t)(m0 + ty * 4 + ii) * N + n0 + tx * 4 + jj] = acc[ii][jj];
}

// per-row Gram, 4x4 register-blocked, symmetric
__global__ void gram_kernel(const float* __restrict__ emb, int ROWS, int which) {
    extern __shared__ float Es[];
    float* out = which ? g_H : g_G;
    int b = blockIdx.x, tid = threadIdx.x;
    int wid = tid >> 5, lane = tid & 31;
    int n = ROWS * ND;
    int np = ROWS * ROWS;
    for (int idx = tid; idx < n; idx += 256) Es[idx] = emb[(size_t)b * n + idx];
    __syncthreads();
    int nt4 = ROWS / 4;
    int count = nt4 * (nt4 + 1) / 2;
    for (int p = wid; p < count; p += 8) {
        int pl = p, tr = 0;
        while (pl >= nt4 - tr) { pl -= nt4 - tr; tr++; }
        int tc = tr + pl;
        const float* E1 = Es + (size_t)tr * 4 * ND;
        const float* E2 = Es + (size_t)tc * 4 * ND;
        float acc[4][4] = {};
        for (int kk = 0; kk < ND; kk += 32) {
            int k = kk + lane;
            float e1[4], e2[4];
#pragma unroll
            for (int j = 0; j < 4; j++) { e1[j] = E1[j * ND + k]; e2[j] = E2[j * ND + k]; }
#pragma unroll
            for (int j = 0; j < 4; j++)
#pragma unroll
                for (int jj = 0; jj < 4; jj++)
                    acc[j][jj] = fmaf(e1[j], e2[jj], acc[j][jj]);
        }
#pragma unroll
        for (int j = 0; j < 4; j++)
#pragma unroll
            for (int jj = 0; jj < 4; jj++) {
#pragma unroll
                for (int o = 16; o; o >>= 1)
                    acc[j][jj] += __shfl_xor_sync(0xffffffffu, acc[j][jj], o);
            }
        if (lane == 0) {
#pragma unroll
            for (int j = 0; j < 4; j++)
#pragma unroll
                for (int jj = 0; jj < 4; jj++) {
                    float v = acc[j][jj];
                    out[(size_t)b * np + (tr * 4 + j) * ROWS + tc * 4 + jj] = v;
                    out[(size_t)b * np + (tc * 4 + jj) * ROWS + tr * 4 + j] = v;
                }
        }
    }
}

// ============================ bf16 cp.async pipelined GEMM (R9 proven config) ============================
#define BM 128
#define BN 256
#define BK 32
#define ASZW (BM * 20)
#define STGW (ASZW + BN * 20)
#define STAGES 4
#define GEMM_SMEM (STAGES * STGW * 4)

__global__ void __launch_bounds__(256, 1) s_gemm(const __nv_bfloat16* __restrict__ Ah,
                                                 const __nv_bfloat16* __restrict__ Bh,
                                                 float* __restrict__ S) {
    extern __shared__ uint32_t smw[];
    uint32_t sb;
    asm("{ .reg .u64 t; cvta.to.shared.u64 t, %1; cvt.u32.u64 %0, t; }" : "=r"(sb) : "l"(smw));
    const int tid = threadIdx.x;
    const int wid = tid >> 5;
    const int lane = tid & 31;
    const int g = lane >> 2;
    const int t = lane & 3;
    const int wm = wid >> 2;
    const int wn = wid & 3;
    const int by = blockIdx.y;
    const int bx = blockIdx.x;
    const int m0 = by * BM;
    const int n0 = bx * BN;
    const bool pBlk = (bx == 40);
    const bool qBlk = (by >= 72);

    const int arow = tid >> 2;
    const int ac = tid & 3;
    const __nv_bfloat16* Agp = (qBlk ? (Ah + (size_t)9216 * ND + (size_t)(by - 72) * BM * ND)
                                     : (Ah + (size_t)m0 * ND)) + (size_t)arow * ND + ac * 8;
    const __nv_bfloat16* Bgp = (pBlk ? (Bh + (size_t)10240 * ND)
                                     : (Bh + (size_t)n0 * ND)) + (size_t)arow * ND + ac * 8;
    const uint32_t sA = sb + (uint32_t)(arow * 20 + ac * 4) * 4;
    const uint32_t sB = sb + (uint32_t)(ASZW + arow * 20 + ac * 4) * 4;

    // ldmatrix lane geometry
    const int alr = (lane & 7) + ((lane >> 3) & 1) * 8;
    const int ahf = (lane >> 4) & 1;
    const int blr = (lane & 7) + ((lane >> 4) & 1) * 8;
    const int bhf = (lane >> 3) & 1;
    const uint32_t aFrag = sb + (uint32_t)(((wm * 64 + alr) * 20) + ahf * 4) * 4;
    const uint32_t bFrag = sb + (uint32_t)((ASZW + (wn * 64 + blr) * 20) + bhf * 4) * 4;

    float cacc[4][8][4];
#pragma unroll
    for (int a = 0; a < 4; a++)
#pragma unroll
        for (int bb = 0; bb < 8; bb++)
#pragma unroll
            for (int cc = 0; cc < 4; cc++) cacc[a][bb][cc] = 0.f;

#define ISSUE(stg, kc) do {                                                    \
    uint32_t so = (uint32_t)(stg) * (STGW * 4);                                \
    _Pragma("unroll")                                                          \
    for (int j = 0; j < 2; j++)                                                \
        cpa16(sA + so + j * (64 * 20 * 4), Agp + (size_t)j * 64 * ND + (kc));  \
    _Pragma("unroll")                                                          \
    for (int j = 0; j < 4; j++)                                                \
        cpa16(sB + so + j * (64 * 20 * 4), Bgp + (size_t)j * 64 * ND + (kc));  \
} while (0)

#define COMPUTE(stg, ks) do {                                                  \
    const uint32_t so = (uint32_t)(stg) * (STGW * 4) + (ks) * 32;              \
    uint32_t af[4][4];                                                         \
    uint32_t bf[8][2];                                                         \
    _Pragma("unroll")                                                          \
    for (int mt = 0; mt < 4; mt++)                                             \
        ldsm_x4(af[mt][0], af[mt][1], af[mt][2], af[mt][3],                    \
                aFrag + so + mt * (16 * 20 * 4));                              \
    _Pragma("unroll")                                                          \
    for (int np = 0; np < 4; np++)                                             \
        ldsm_x4(bf[2 * np][0], bf[2 * np][1], bf[2 * np + 1][0],               \
                bf[2 * np + 1][1], bFrag + so + np * (16 * 20 * 4));           \
    _Pragma("unroll")                                                          \
    for (int mt = 0; mt < 4; mt++)                                             \
        _Pragma("unroll")                                                      \
        for (int nt = 0; nt < 8; nt++)                                         \
            mma_bf16(cacc[mt][nt], af[mt], bf[nt]);                            \
} while (0)

    ISSUE(0, 0);  asm volatile("cp.async.commit_group;" ::: "memory");
    ISSUE(1, 32); asm volatile("cp.async.commit_group;" ::: "memory");
    ISSUE(2, 64); asm volatile("cp.async.commit_group;" ::: "memory");

#pragma unroll 1
    for (int c = 0; c < 32; c++) {
        asm volatile("cp.async.wait_group 2;" ::: "memory");
        __syncthreads();
        COMPUTE(c & 3, 0);
        COMPUTE(c & 3, 1);
        if (c < 29) ISSUE((c + 3) & 3, (c + 3) * BK);
        asm volatile("cp.async.commit_group;" ::: "memory");
    }

    if (pBlk && qBlk) return;

    if (!pBlk && !qBlk) {
#pragma unroll
        for (int mt = 0; mt < 4; mt++) {
            int m = m0 + wm * 64 + mt * 16 + g;
#pragma unroll
            for (int nt = 0; nt < 8; nt++) {
                int n = n0 + wn * 64 + nt * 8 + 2 * t;
                float v0 = cacc[mt][nt][0]; v0 = (v0 >= 0.f) ? v0 : 0.1f * v0;
                float v1 = cacc[mt][nt][1]; v1 = (v1 >= 0.f) ? v1 : 0.1f * v1;
                float v2 = cacc[mt][nt][2]; v2 = (v2 >= 0.f) ? v2 : 0.1f * v2;
                float v3 = cacc[mt][nt][3]; v3 = (v3 >= 0.f) ? v3 : 0.1f * v3;
                __stcs(S + (size_t)n * MT + m, v0);
                __stcs(S + (size_t)(n + 1) * MT + m, v1);
                __stcs(S + (size_t)n * MT + m + 8, v2);
                __stcs(S + (size_t)(n + 1) * MT + m + 8, v3);
            }
        }
    } else if (pBlk) {
#pragma unroll
        for (int mt = 0; mt < 4; mt++) {
            int m = m0 + wm * 64 + mt * 16 + g;
#pragma unroll
            for (int nt = 0; nt < 8; nt++) {
                int i = wn * 64 + nt * 8 + 2 * t;
                __stcs(g_P + (size_t)i * MT + m, cacc[mt][nt][0]);
                __stcs(g_P + (size_t)(i + 1) * MT + m, cacc[mt][nt][1]);
                __stcs(g_P + (size_t)i * MT + m + 8, cacc[mt][nt][2]);
                __stcs(g_P + (size_t)(i + 1) * MT + m + 8, cacc[mt][nt][3]);
            }
        }
    } else {
#pragma unroll
        for (int mt = 0; mt < 4; mt++) {
            int b = (by - 72) * BM + wm * 64 + mt * 16 + g;
#pragma unroll
            for (int nt = 0; nt < 8; nt++) {
                int n = n0 + wn * 64 + nt * 8 + 2 * t;
                __stcs(g_Q + (size_t)b * NT + n, cacc[mt][nt][0]);
                __stcs(g_Q + (size_t)b * NT + n + 1, cacc[mt][nt][1]);
                __stcs(g_Q + (size_t)(b + 8) * NT + n, cacc[mt][nt][2]);
                __stcs(g_Q + (size_t)(b + 8) * NT + n + 1, cacc[mt][nt][3]);
            }
        }
    }
#undef ISSUE
#undef COMPUTE
}

// ============================ per-pair epilogue: R7/R9 body, float4 global loads ============================
// word offsets: FS 0 (40x37=1480, [l][r]) | Am 1480 (40x44) | Cm 3240 (36x44)
//               Hs 4824 (40x40) | Gs 6424 (36x36) | w2p1 7720 (40x9) | w2p2 8080 (36x10)
#define EPI_WORDS 8440
#define EPI_SMEM (EPI_WORDS * 4)

__global__ void __launch_bounds__(128) pair_epilogue(const float* __restrict__ S,
                                                     float* __restrict__ out) {
    extern __shared__ float sh[];
    __shared__ float Pb[NR], Qi[NL], rnl[NR], cnl[NL], s1s[NL], s2s[NR];
    float* FS = sh;          // [l][r] stride 37
    float* Am = sh + 1480;
    float* Cm = sh + 3240;
    float* Hs = sh + 4824;
    float* Gs = sh + 6424;
    float* w2p1 = sh + 7720;
    float* w2p2 = sh + 8080;
    const int i = blockIdx.x, b = blockIdx.y, tid = threadIdx.x;

    // --- vectorized global loads (MLP_p1 reduction) ---
    const float* Sp = S + (size_t)i * NL * MT + (size_t)b * NR;   // 16B-aligned rows
    for (int q = tid; q < 360; q += 128) {                        // FS: 360 float4
        int l = q / 9, sg = q - l * 9;
        float4 v = ldg4(Sp + (size_t)l * MT + sg * 4);
        float* d = FS + l * 37 + sg * 4;
        d[0] = v.x; d[1] = v.y; d[2] = v.z; d[3] = v.w;
    }
    {
        const float4* Gg = (const float4*)(g_G + (size_t)b * (NR * NR));
        for (int q = tid; q < 324; q += 128) ((float4*)Gs)[q] = Gg[q];
        const float4* Hg = (const float4*)(g_H + (size_t)i * (NL * NL));
        for (int q = tid; q < 400; q += 128) ((float4*)Hs)[q] = Hg[q];
    }
    if (tid < 9) {
        float4 v = ldg4(g_P + (size_t)i * MT + b * NR + tid * 4);
        Pb[tid * 4 + 0] = v.x; Pb[tid * 4 + 1] = v.y;
        Pb[tid * 4 + 2] = v.z; Pb[tid * 4 + 3] = v.w;
    } else if (tid >= 64 && tid < 74) {
        int q = tid - 64;
        float4 v = ldg4(g_Q + (size_t)b * NT + i * NL + q * 4);
        Qi[q * 4 + 0] = v.x; Qi[q * 4 + 1] = v.y;
        Qi[q * 4 + 2] = v.z; Qi[q * 4 + 3] = v.w;
    }
    __syncthreads();

    if (tid < NL) {                         // per-l norm over r -> lambda/cn
        int l = tid; float s = 0.f;
#pragma unroll
        for (int r = 0; r < NR; r++) { float v = FS[l * 37 + r]; s = fmaf(v, v, s); }
        cnl[l] = LAMS / (sqrtf(s) + EPSF);
    } else if (tid >= 64 && tid < 64 + NR) { // per-r norm over l -> lambda/rn
        int r = tid - 64; float s = 0.f;
#pragma unroll
        for (int l = 0; l < NL; l++) { float v = FS[l * 37 + r]; s = fmaf(v, v, s); }
        rnl[r] = LAMS / (sqrtf(s) + EPSF);
    }
    __syncthreads();

    for (int idx = tid; idx < NR * NL; idx += 128) {
        int l = idx / NR, r = idx - l * NR;
        float v = FS[l * 37 + r];
        Am[l * 44 + r] = __expf(v * rnl[r]);
        Cm[r * 44 + l] = __expf(v * cnl[l]);
    }
    __syncthreads();

    // fused mini-GEMM + quadratic form: 180 tasks, each a 4x4 tile (R7 proven)
    for (int task = tid; task < 180; task += 128) {
        float4 acc0 = make_float4(0.f, 0.f, 0.f, 0.f);
        float4 acc1 = acc0, acc2 = acc0, acc3 = acc0;
        float4 st0 = acc0, st1 = acc0, st2 = acc0, st3 = acc0;
        if (task < 90) {
            int lg = task / 9, rg = task - lg * 9;
            const float* Ab = Am + lg * 4 * 44;
            const float* Gb = Gs + rg * 4;
#pragma unroll
            for (int rp4 = 0; rp4 < 9; rp4++) {
                float4 a0 = *(const float4*)(Ab + rp4 * 4);
                float4 a1 = *(const float4*)(Ab + 44 + rp4 * 4);
                float4 a2 = *(const float4*)(Ab + 88 + rp4 * 4);
                float4 a3 = *(const float4*)(Ab + 132 + rp4 * 4);
                if (rp4 == rg) { st0 = a0; st1 = a1; st2 = a2; st3 = a3; }
                float4 g0 = *(const float4*)(Gb + (rp4 * 4 + 0) * 36);
                float4 g1 = *(const float4*)(Gb + (rp4 * 4 + 1) * 36);
                float4 g2 = *(const float4*)(Gb + (rp4 * 4 + 2) * 36);
                float4 g3 = *(const float4*)(Gb + (rp4 * 4 + 3) * 36);
#define ACC4(ACC, AV)                                                          \
                ACC.x = fmaf(AV.x, g0.x, ACC.x); ACC.y = fmaf(AV.x, g0.y, ACC.y); \
                ACC.z = fmaf(AV.x, g0.z, ACC.z); ACC.w = fmaf(AV.x, g0.w, ACC.w); \
                ACC.x = fmaf(AV.y, g1.x, ACC.x); ACC.y = fmaf(AV.y, g1.y, ACC.y); \
                ACC.z = fmaf(AV.y, g1.z, ACC.z); ACC.w = fmaf(AV.y, g1.w, ACC.w); \
                ACC.x = fmaf(AV.z, g2.x, ACC.x); ACC.y = fmaf(AV.z, g2.y, ACC.y); \
                ACC.z = fmaf(AV.z, g2.z, ACC.z); ACC.w = fmaf(AV.z, g2.w, ACC.w); \
                ACC.x = fmaf(AV.w, g3.x, ACC.x); ACC.y = fmaf(AV.w, g3.y, ACC.y); \
                ACC.z = fmaf(AV.w, g3.z, ACC.z); ACC.w = fmaf(AV.w, g3.w, ACC.w);
                ACC4(acc0, a0) ACC4(acc1, a1) ACC4(acc2, a2) ACC4(acc3, a3)
            }
            int l = lg * 4;
            w2p1[(l + 0) * 9 + rg] = acc0.x * st0.x + acc0.y * st0.y + acc0.z * st0.z + acc0.w * st0.w;
            w2p1[(l + 1) * 9 + rg] = acc1.x * st1.x + acc1.y * st1.y + acc1.z * st1.z + acc1.w * st1.w;
            w2p1[(l + 2) * 9 + rg] = acc2.x * st2.x + acc2.y * st2.y + acc2.z * st2.z + acc2.w * st2.w;
            w2p1[(l + 3) * 9 + rg] = acc3.x * st3.x + acc3.y * st3.y + acc3.z * st3.z + acc3.w * st3.w;
        } else {
            int t2 = task - 90;
            int rg = t2 / 10, lg = t2 - rg * 10;
            const float* Cb = Cm + rg * 4 * 44;
            const float* Hb = Hs + lg * 4;
#pragma unroll
            for (int lp4 = 0; lp4 < 10; lp4++) {
                float4 a0 = *(const float4*)(Cb + lp4 * 4);
                float4 a1 = *(const float4*)(Cb + 44 + lp4 * 4);
                float4 a2 = *(const float4*)(Cb + 88 + lp4 * 4);
                float4 a3 = *(const float4*)(Cb + 132 + lp4 * 4);
                if (lp4 == lg) { st0 = a0; st1 = a1; st2 = a2; st3 = a3; }
                float4 g0 = *(const float4*)(Hb + (lp4 * 4 + 0) * 40);
                float4 g1 = *(const float4*)(Hb + (lp4 * 4 + 1) * 40);
                float4 g2 = *(const float4*)(Hb + (lp4 * 4 + 2) * 40);
                float4 g3 = *(const float4*)(Hb + (lp4 * 4 + 3) * 40);
                ACC4(acc0, a0) ACC4(acc1, a1) ACC4(acc2, a2) ACC4(acc3, a3)
#undef ACC4
            }
            int r = rg * 4;
            w2p2[(r + 0) * 10 + lg] = acc0.x * st0.x + acc0.y * st0.y + acc0.z * st0.z + acc0.w * st0.w;
            w2p2[(r + 1) * 10 + lg] = acc1.x * st1.x + acc1.y * st1.y + acc1.z * st1.z + acc1.w * st1.w;
            w2p2[(r + 2) * 10 + lg] = acc2.x * st2.x + acc2.y * st2.y + acc2.z * st2.z + acc2.w * st2.w;
            w2p2[(r + 3) * 10 + lg] = acc3.x * st3.x + acc3.y * st3.y + acc3.z * st3.z + acc3.w * st3.w;
        }
    }
    __syncthreads();

    if (tid < NL) {                          // t2i: word l
        int l = tid; float w12 = 0.f, w2 = 0.f;
#pragma unroll
        for (int r = 0; r < NR; r++) w12 = fmaf(Am[l * 44 + r], Pb[r], w12);
#pragma unroll
        for (int k = 0; k < 9; k++) w2 += w2p1[l * 9 + k];
        float den = fmaxf(g_w1t[i] * sqrtf(fmaxf(w2, 0.f)), EPSF);
        s1s[l] = __fdividef(w12, den);
    } else if (tid >= 64 && tid < 64 + NR) { // i2t: region r
        int r = tid - 64; float w12 = 0.f, w2 = 0.f;
#pragma unroll
        for (int l = 0; l < NL; l++) w12 = fmaf(Cm[r * 44 + l], Qi[l], w12);
#pragma unroll
        for (int k = 0; k < 10; k++) w2 += w2p2[r * 10 + k];
        float den = fmaxf(g_w1i[b] * sqrtf(fmaxf(w2, 0.f)), EPSF);
        s2s[r] = __fdividef(w12, den);
    }
    __syncthreads();

    if (tid == 0) {
        float m1 = 0.f, m2 = 0.f;
#pragma unroll
        for (int l = 0; l < NL; l++) m1 += s1s[l];
#pragma unroll
        for (int r = 0; r < NR; r++) m2 += s2s[r];
        out[(size_t)b * NB + i] = g_base[b * NB + i] + m1 * (1.f / NL) + m2 * (1.f / NR);
    }
}

// ============================ launch ============================
extern "C" void kernel_launch(void* const* d_in, const int* in_sizes, int n_in,
                              void* d_out, int out_size) {
    (void)in_sizes; (void)n_in; (void)out_size;
    const float* pool_img = (const float*)d_in[0];
    const float* img_emb  = (const float*)d_in[1];
    const float* pool_txt = (const float*)d_in[2];
    const float* cap_emb  = (const float*)d_in[3];
    float* out = (float*)d_out;

    cudaFuncSetAttribute((const void*)gram_kernel,
                         cudaFuncAttributeMaxDynamicSharedMemorySize, NL * ND * 4);
    cudaFuncSetAttribute((const void*)s_gemm,
                         cudaFuncAttributeMaxDynamicSharedMemorySize, GEMM_SMEM);
    cudaFuncSetAttribute((const void*)pair_epilogue,
                         cudaFuncAttributeMaxDynamicSharedMemorySize, EPI_SMEM);

    float* dS = nullptr;
    cudaGetSymbolAddress((void**)&dS, g_S);
    __nv_bfloat16* dAh = nullptr; cudaGetSymbolAddress((void**)&dAh, g_Ah);
    __nv_bfloat16* dBh = nullptr; cudaGetSymbolAddress((void**)&dBh, g_Bh);

    // order: s_gemm stays at launch index 3 (profiled slot)
    cvt_kernel<<<9984, 256>>>(img_emb, pool_img, cap_emb, pool_txt);
    gram_kernel<<<NB, 256, NR * ND * 4>>>(img_emb, NR, 0);
    gram_kernel<<<NB, 256, NL * ND * 4>>>(cap_emb, NL, 1);
    s_gemm<<<dim3(41, 74), 256, GEMM_SMEM>>>(dAh, dBh, dS);
    norm_kernel<<<64, 256>>>(pool_img, pool_txt);
    sgemm_tn<<<dim3(NB / 64, NB / 64), 256>>>(pool_img, pool_txt, NB, NB, ND);
    pair_epilogue<<<dim3(NB, NB), 128, EPI_SMEM>>>(dS, out);
}

// round 14
// speedup vs baseline: 1.7457x; 1.0477x over previous
#include <cuda_runtime.h>
#include <cuda_bf16.h>
#include <math.h>
#include <cstdint>

#define NB 256
#define NR 36
#define NL 40
#define ND 1024
#define MT (NB * NR)   /* 9216  */
#define NT (NB * NL)   /* 10240 */
#define EPSF 1e-8f
#define LAMS 9.0f

#define MROWS 9472     /* 9216 img rows + 256 pool_img */
#define NROWS 10496    /* 10240 cap rows + 256 pool_txt */

// ---- scratch (device globals; no allocation allowed) ----
__device__ float g_S[(size_t)MT * NT];           // S^T[n][m], leaky-relu'd (378MB)
__device__ __nv_bfloat16 g_Ah[(size_t)MROWS * ND];  // bf16 img_emb ++ pool_img
__device__ __nv_bfloat16 g_Bh[(size_t)NROWS * ND];  // bf16 cap_emb ++ pool_txt
__device__ float g_P[NB * NB * NR];
__device__ float g_Q[NB * NB * NL];
__device__ float g_G[NB * NR * NR];
__device__ float g_H[NB * NL * NL];
__device__ float g_base[NB * NB];
__device__ float g_w1i[NB];
__device__ float g_w1t[NB];

__device__ __forceinline__ float4 ldg4(const float* p) {
    return *reinterpret_cast<const float4*>(p);
}
__device__ __forceinline__ uint32_t pack_bf2(float x, float y) {
    __nv_bfloat162 h = __float22bfloat162_rn(make_float2(x, y));
    return *reinterpret_cast<uint32_t*>(&h);
}
__device__ __forceinline__ void mma_bf16(float* c, const uint32_t* a, const uint32_t* b) {
    asm volatile(
        "mma.sync.aligned.m16n8k16.row.col.f32.bf16.bf16.f32 "
        "{%0,%1,%2,%3}, {%4,%5,%6,%7}, {%8,%9}, {%0,%1,%2,%3};"
        : "+f"(c[0]), "+f"(c[1]), "+f"(c[2]), "+f"(c[3])
        : "r"(a[0]), "r"(a[1]), "r"(a[2]), "r"(a[3]), "r"(b[0]), "r"(b[1]));
}
__device__ __forceinline__ void cpa16(uint32_t saddr, const void* gaddr) {
    asm volatile("cp.async.ca.shared.global [%0], [%1], 16;"
                 :: "r"(saddr), "l"(gaddr) : "memory");
}
__device__ __forceinline__ void ldsm_x4(uint32_t& r0, uint32_t& r1, uint32_t& r2,
                                        uint32_t& r3, uint32_t addr) {
    asm volatile("ldmatrix.sync.aligned.m8n8.x4.shared.b16 {%0,%1,%2,%3}, [%4];"
                 : "=r"(r0), "=r"(r1), "=r"(r2), "=r"(r3) : "r"(addr));
}

// ============================ bf16 conversion (augmented operands) ============================
__global__ void cvt_kernel(const float* __restrict__ img, const float* __restrict__ pimg,
                           const float* __restrict__ cap, const float* __restrict__ ptxt) {
    size_t g8 = (size_t)blockIdx.x * 256 + threadIdx.x;
    const size_t A8 = (size_t)MROWS * (ND / 8);
    const float* src;
    uint32_t* dst;
    if (g8 < A8) {
        size_t off = g8 * 8;
        size_t row = off >> 10, col = off & 1023;
        src = (row < 9216) ? (img + row * ND + col) : (pimg + (row - 9216) * ND + col);
        dst = reinterpret_cast<uint32_t*>(g_Ah) + g8 * 4;
    } else {
        size_t h8 = g8 - A8;
        size_t off = h8 * 8;
        size_t row = off >> 10, col = off & 1023;
        src = (row < 10240) ? (cap + row * ND + col) : (ptxt + (row - 10240) * ND + col);
        dst = reinterpret_cast<uint32_t*>(g_Bh) + h8 * 4;
    }
    float4 x = ldg4(src), y = ldg4(src + 4);
    *reinterpret_cast<uint4*>(dst) =
        make_uint4(pack_bf2(x.x, x.y), pack_bf2(x.z, x.w),
                   pack_bf2(y.x, y.y), pack_bf2(y.z, y.w));
}

// ============================ precompute kernels ============================
__global__ void norm_kernel(const float* __restrict__ pi, const float* __restrict__ pt) {
    int w = blockIdx.x * 8 + (threadIdx.x >> 5);
    int lane = threadIdx.x & 31;
    const float* src = (w < NB) ? (pi + (size_t)w * ND) : (pt + (size_t)(w - NB) * ND);
    float s = 0.f;
    for (int j = lane; j < ND; j += 32) { float v = src[j]; s = fmaf(v, v, s); }
#pragma unroll
    for (int o = 16; o; o >>= 1) s += __shfl_down_sync(0xffffffffu, s, o);
    if (lane == 0) {
        float r = sqrtf(s);
        if (w < NB) g_w1i[w] = r; else g_w1t[w - NB] = r;
    }
}

__global__ void sgemm_tn(const float* __restrict__ A, const float* __restrict__ Bm,
                         int M, int N, int K) {
    float* C = g_base;
    __shared__ float As[16 * 64];
    __shared__ float Bs[16 * 64];
    int tid = threadIdx.x;
    int tx = tid & 15, ty = tid >> 4;
    int m0 = blockIdx.y * 64, n0 = blockIdx.x * 64;
    int row = tid >> 2, q = tid & 3;
    float acc[4][4] = {};
    for (int k0 = 0; k0 < K; k0 += 16) {
        float4 a = ldg4(A + (size_t)(m0 + row) * K + k0 + q * 4);
        float4 bb = ldg4(Bm + (size_t)(n0 + row) * K + k0 + q * 4);
        As[(q * 4 + 0) * 64 + row] = a.x;  As[(q * 4 + 1) * 64 + row] = a.y;
        As[(q * 4 + 2) * 64 + row] = a.z;  As[(q * 4 + 3) * 64 + row] = a.w;
        Bs[(q * 4 + 0) * 64 + row] = bb.x; Bs[(q * 4 + 1) * 64 + row] = bb.y;
        Bs[(q * 4 + 2) * 64 + row] = bb.z; Bs[(q * 4 + 3) * 64 + row] = bb.w;
        __syncthreads();
#pragma unroll
        for (int k = 0; k < 16; k++) {
            float4 av = *(const float4*)(As + k * 64 + ty * 4);
            float4 bv = *(const float4*)(Bs + k * 64 + tx * 4);
            float aa[4] = {av.x, av.y, av.z, av.w};
            float bw[4] = {bv.x, bv.y, bv.z, bv.w};
#pragma unroll
            for (int ii = 0; ii < 4; ii++)
#pragma unroll
                for (int jj = 0; jj < 4; jj++)
                    acc[ii][jj] = fmaf(aa[ii], bw[jj], acc[ii][jj]);
        }
        __syncthreads();
    }
#pragma unroll
    for (int ii = 0; ii < 4; ii++)
#pragma unroll
        for (int jj = 0; jj < 4; jj++)
            C[(size_t)(m0 + ty * 4 + ii) * N + n0 + tx * 4 + jj] = acc[ii][jj];
}

// per-row Gram, 4x4 register-blocked, symmetric
__global__ void gram_kernel(const float* __restrict__ emb, int ROWS, int which) {
    extern __shared__ float Es[];
    float* out = which ? g_H : g_G;
    int b = blockIdx.x, tid = threadIdx.x;
    int wid = tid >> 5, lane = tid & 31;
    int n = ROWS * ND;
    int np = ROWS * ROWS;
    for (int idx = tid; idx < n; idx += 256) Es[idx] = emb[(size_t)b * n + idx];
    __syncthreads();
    int nt4 = ROWS / 4;
    int count = nt4 * (nt4 + 1) / 2;
    for (int p = wid; p < count; p += 8) {
        int pl = p, tr = 0;
        while (pl >= nt4 - tr) { pl -= nt4 - tr; tr++; }
        int tc = tr + pl;
        const float* E1 = Es + (size_t)tr * 4 * ND;
        const float* E2 = Es + (size_t)tc * 4 * ND;
        float acc[4][4] = {};
        for (int kk = 0; kk < ND; kk += 32) {
            int k = kk + lane;
            float e1[4], e2[4];
#pragma unroll
            for (int j = 0; j < 4; j++) { e1[j] = E1[j * ND + k]; e2[j] = E2[j * ND + k]; }
#pragma unroll
            for (int j = 0; j < 4; j++)
#pragma unroll
                for (int jj = 0; jj < 4; jj++)
                    acc[j][jj] = fmaf(e1[j], e2[jj], acc[j][jj]);
        }
#pragma unroll
        for (int j = 0; j < 4; j++)
#pragma unroll
            for (int jj = 0; jj < 4; jj++) {
#pragma unroll
                for (int o = 16; o; o >>= 1)
                    acc[j][jj] += __shfl_xor_sync(0xffffffffu, acc[j][jj], o);
            }
        if (lane == 0) {
#pragma unroll
            for (int j = 0; j < 4; j++)
#pragma unroll
                for (int jj = 0; jj < 4; jj++) {
                    float v = acc[j][jj];
                    out[(size_t)b * np + (tr * 4 + j) * ROWS + tc * 4 + jj] = v;
                    out[(size_t)b * np + (tc * 4 + jj) * ROWS + tr * 4 + j] = v;
                }
        }
    }
}

// ============================ bf16 cp.async GEMM: BK=64, 3 stages, half the barriers ============================
#define BM 128
#define BN 256
#define BK 64
#define ASZW (BM * 36)              /* 4608 words */
#define STGW (ASZW + BN * 36)       /* 13824 words = 55296 B */
#define STAGES 3
#define GEMM_SMEM (STAGES * STGW * 4)   /* 165888 B */

__global__ void __launch_bounds__(256, 1) s_gemm(const __nv_bfloat16* __restrict__ Ah,
                                                 const __nv_bfloat16* __restrict__ Bh,
                                                 float* __restrict__ S) {
    extern __shared__ uint32_t smw[];
    uint32_t sb;
    asm("{ .reg .u64 t; cvta.to.shared.u64 t, %1; cvt.u32.u64 %0, t; }" : "=r"(sb) : "l"(smw));
    const int tid = threadIdx.x;
    const int wid = tid >> 5;
    const int lane = tid & 31;
    const int g = lane >> 2;
    const int t = lane & 3;
    const int wm = wid >> 2;
    const int wn = wid & 3;
    const int by = blockIdx.y;
    const int bx = blockIdx.x;
    const int m0 = by * BM;
    const int n0 = bx * BN;
    const bool pBlk = (bx == 40);
    const bool qBlk = (by >= 72);

    // cp.async lane geometry: row = tid>>3 (+32j), 16B chunk = tid&7
    const int r0 = tid >> 3;
    const int c0 = tid & 7;
    const __nv_bfloat16* Agp = (qBlk ? (Ah + (size_t)9216 * ND + (size_t)(by - 72) * BM * ND)
                                     : (Ah + (size_t)m0 * ND)) + (size_t)r0 * ND + c0 * 8;
    const __nv_bfloat16* Bgp = (pBlk ? (Bh + (size_t)10240 * ND)
                                     : (Bh + (size_t)n0 * ND)) + (size_t)r0 * ND + c0 * 8;
    const uint32_t sA = sb + (uint32_t)(r0 * 144 + c0 * 16);
    const uint32_t sB = sb + (uint32_t)(ASZW * 4 + r0 * 144 + c0 * 16);

    // ldmatrix lane geometry (rows stride 144B; k-half selects 16B)
    const int alr = (lane & 7) + ((lane >> 3) & 1) * 8;
    const int ahf = (lane >> 4) & 1;
    const int blr = (lane & 7) + ((lane >> 4) & 1) * 8;
    const int bhf = (lane >> 3) & 1;
    const uint32_t aFrag = sb + (uint32_t)((wm * 64 + alr) * 144 + ahf * 16);
    const uint32_t bFrag = sb + (uint32_t)(ASZW * 4 + (wn * 64 + blr) * 144 + bhf * 16);

    float cacc[4][8][4];
#pragma unroll
    for (int a = 0; a < 4; a++)
#pragma unroll
        for (int bb = 0; bb < 8; bb++)
#pragma unroll
            for (int cc = 0; cc < 4; cc++) cacc[a][bb][cc] = 0.f;

#define ISSUE(stg, kc) do {                                                    \
    uint32_t so = (uint32_t)(stg) * (STGW * 4);                                \
    _Pragma("unroll")                                                          \
    for (int j = 0; j < 4; j++)                                                \
        cpa16(sA + so + j * (32 * 144), Agp + (size_t)j * 32 * ND + (kc));     \
    _Pragma("unroll")                                                          \
    for (int j = 0; j < 8; j++)                                                \
        cpa16(sB + so + j * (32 * 144), Bgp + (size_t)j * 32 * ND + (kc));     \
} while (0)

#define COMPUTE(stg, ks) do {                                                  \
    const uint32_t so = (uint32_t)(stg) * (STGW * 4) + (ks) * 32;              \
    uint32_t af[4][4];                                                         \
    uint32_t bf[8][2];                                                         \
    _Pragma("unroll")                                                          \
    for (int mt = 0; mt < 4; mt++)                                             \
        ldsm_x4(af[mt][0], af[mt][1], af[mt][2], af[mt][3],                    \
                aFrag + so + mt * (16 * 144));                                 \
    _Pragma("unroll")                                                          \
    for (int np = 0; np < 4; np++)                                             \
        ldsm_x4(bf[2 * np][0], bf[2 * np][1], bf[2 * np + 1][0],               \
                bf[2 * np + 1][1], bFrag + so + np * (16 * 144));              \
    _Pragma("unroll")                                                          \
    for (int mt = 0; mt < 4; mt++)                                             \
        _Pragma("unroll")                                                      \
        for (int nt = 0; nt < 8; nt++)                                         \
            mma_bf16(cacc[mt][nt], af[mt], bf[nt]);                            \
} while (0)

    ISSUE(0, 0);  asm volatile("cp.async.commit_group;" ::: "memory");
    ISSUE(1, 64); asm volatile("cp.async.commit_group;" ::: "memory");

#pragma unroll 1
    for (int c = 0; c < 16; c++) {
        asm volatile("cp.async.wait_group 1;" ::: "memory");
        __syncthreads();
        int st = c % 3;
        COMPUTE(st, 0);
        COMPUTE(st, 1);
        COMPUTE(st, 2);
        COMPUTE(st, 3);
        if (c < 14) ISSUE((c + 2) % 3, (c + 2) * BK);
        asm volatile("cp.async.commit_group;" ::: "memory");
    }

    if (pBlk && qBlk) return;

    if (!pBlk && !qBlk) {
#pragma unroll
        for (int mt = 0; mt < 4; mt++) {
            int m = m0 + wm * 64 + mt * 16 + g;
#pragma unroll
            for (int nt = 0; nt < 8; nt++) {
                int n = n0 + wn * 64 + nt * 8 + 2 * t;
                float v0 = cacc[mt][nt][0]; v0 = (v0 >= 0.f) ? v0 : 0.1f * v0;
                float v1 = cacc[mt][nt][1]; v1 = (v1 >= 0.f) ? v1 : 0.1f * v1;
                float v2 = cacc[mt][nt][2]; v2 = (v2 >= 0.f) ? v2 : 0.1f * v2;
                float v3 = cacc[mt][nt][3]; v3 = (v3 >= 0.f) ? v3 : 0.1f * v3;
                __stcs(S + (size_t)n * MT + m, v0);
                __stcs(S + (size_t)(n + 1) * MT + m, v1);
                __stcs(S + (size_t)n * MT + m + 8, v2);
                __stcs(S + (size_t)(n + 1) * MT + m + 8, v3);
            }
        }
    } else if (pBlk) {
#pragma unroll
        for (int mt = 0; mt < 4; mt++) {
            int m = m0 + wm * 64 + mt * 16 + g;
#pragma unroll
            for (int nt = 0; nt < 8; nt++) {
                int i = wn * 64 + nt * 8 + 2 * t;
                __stcs(g_P + (size_t)i * MT + m, cacc[mt][nt][0]);
                __stcs(g_P + (size_t)(i + 1) * MT + m, cacc[mt][nt][1]);
                __stcs(g_P + (size_t)i * MT + m + 8, cacc[mt][nt][2]);
                __stcs(g_P + (size_t)(i + 1) * MT + m + 8, cacc[mt][nt][3]);
            }
        }
    } else {
#pragma unroll
        for (int mt = 0; mt < 4; mt++) {
            int b = (by - 72) * BM + wm * 64 + mt * 16 + g;
#pragma unroll
            for (int nt = 0; nt < 8; nt++) {
                int n = n0 + wn * 64 + nt * 8 + 2 * t;
                __stcs(g_Q + (size_t)b * NT + n, cacc[mt][nt][0]);
                __stcs(g_Q + (size_t)b * NT + n + 1, cacc[mt][nt][1]);
                __stcs(g_Q + (size_t)(b + 8) * NT + n, cacc[mt][nt][2]);
                __stcs(g_Q + (size_t)(b + 8) * NT + n + 1, cacc[mt][nt][3]);
            }
        }
    }
#undef ISSUE
#undef COMPUTE
}

// ============================ per-pair epilogue (R13 proven version, unchanged) ============================
// word offsets: FS 0 (40x37=1480, [l][r]) | Am 1480 (40x44) | Cm 3240 (36x44)
//               Hs 4824 (40x40) | Gs 6424 (36x36) | w2p1 7720 (40x9) | w2p2 8080 (36x10)
#define EPI_WORDS 8440
#define EPI_SMEM (EPI_WORDS * 4)

__global__ void __launch_bounds__(128) pair_epilogue(const float* __restrict__ S,
                                                     float* __restrict__ out) {
    extern __shared__ float sh[];
    __shared__ float Pb[NR], Qi[NL], rnl[NR], cnl[NL], s1s[NL], s2s[NR];
    float* FS = sh;          // [l][r] stride 37
    float* Am = sh + 1480;
    float* Cm = sh + 3240;
    float* Hs = sh + 4824;
    float* Gs = sh + 6424;
    float* w2p1 = sh + 7720;
    float* w2p2 = sh + 8080;
    const int i = blockIdx.x, b = blockIdx.y, tid = threadIdx.x;

    // --- vectorized global loads (MLP_p1 reduction) ---
    const float* Sp = S + (size_t)i * NL * MT + (size_t)b * NR;
    for (int q = tid; q < 360; q += 128) {
        int l = q / 9, sg = q - l * 9;
        float4 v = ldg4(Sp + (size_t)l * MT + sg * 4);
        float* d = FS + l * 37 + sg * 4;
        d[0] = v.x; d[1] = v.y; d[2] = v.z; d[3] = v.w;
    }
    {
        const float4* Gg = (const float4*)(g_G + (size_t)b * (NR * NR));
        for (int q = tid; q < 324; q += 128) ((float4*)Gs)[q] = Gg[q];
        const float4* Hg = (const float4*)(g_H + (size_t)i * (NL * NL));
        for (int q = tid; q < 400; q += 128) ((float4*)Hs)[q] = Hg[q];
    }
    if (tid < 9) {
        float4 v = ldg4(g_P + (size_t)i * MT + b * NR + tid * 4);
        Pb[tid * 4 + 0] = v.x; Pb[tid * 4 + 1] = v.y;
        Pb[tid * 4 + 2] = v.z; Pb[tid * 4 + 3] = v.w;
    } else if (tid >= 64 && tid < 74) {
        int q = tid - 64;
        float4 v = ldg4(g_Q + (size_t)b * NT + i * NL + q * 4);
        Qi[q * 4 + 0] = v.x; Qi[q * 4 + 1] = v.y;
        Qi[q * 4 + 2] = v.z; Qi[q * 4 + 3] = v.w;
    }
    __syncthreads();

    if (tid < NL) {
        int l = tid; float s = 0.f;
#pragma unroll
        for (int r = 0; r < NR; r++) { float v = FS[l * 37 + r]; s = fmaf(v, v, s); }
        cnl[l] = LAMS / (sqrtf(s) + EPSF);
    } else if (tid >= 64 && tid < 64 + NR) {
        int r = tid - 64; float s = 0.f;
#pragma unroll
        for (int l = 0; l < NL; l++) { float v = FS[l * 37 + r]; s = fmaf(v, v, s); }
        rnl[r] = LAMS / (sqrtf(s) + EPSF);
    }
    __syncthreads();

    for (int idx = tid; idx < NR * NL; idx += 128) {
        int l = idx / NR, r = idx - l * NR;
        float v = FS[l * 37 + r];
        Am[l * 44 + r] = __expf(v * rnl[r]);
        Cm[r * 44 + l] = __expf(v * cnl[l]);
    }
    __syncthreads();

    // fused mini-GEMM + quadratic form: 180 tasks, each a 4x4 tile
    for (int task = tid; task < 180; task += 128) {
        float4 acc0 = make_float4(0.f, 0.f, 0.f, 0.f);
        float4 acc1 = acc0, acc2 = acc0, acc3 = acc0;
        float4 st0 = acc0, st1 = acc0, st2 = acc0, st3 = acc0;
        if (task < 90) {
            int lg = task / 9, rg = task - lg * 9;
            const float* Ab = Am + lg * 4 * 44;
            const float* Gb = Gs + rg * 4;
#pragma unroll
            for (int rp4 = 0; rp4 < 9; rp4++) {
                float4 a0 = *(const float4*)(Ab + rp4 * 4);
                float4 a1 = *(const float4*)(Ab + 44 + rp4 * 4);
                float4 a2 = *(const float4*)(Ab + 88 + rp4 * 4);
                float4 a3 = *(const float4*)(Ab + 132 + rp4 * 4);
                if (rp4 == rg) { st0 = a0; st1 = a1; st2 = a2; st3 = a3; }
                float4 g0 = *(const float4*)(Gb + (rp4 * 4 + 0) * 36);
                float4 g1 = *(const float4*)(Gb + (rp4 * 4 + 1) * 36);
                float4 g2 = *(const float4*)(Gb + (rp4 * 4 + 2) * 36);
                float4 g3 = *(const float4*)(Gb + (rp4 * 4 + 3) * 36);
#define ACC4(ACC, AV)                                                          \
                ACC.x = fmaf(AV.x, g0.x, ACC.x); ACC.y = fmaf(AV.x, g0.y, ACC.y); \
                ACC.z = fmaf(AV.x, g0.z, ACC.z); ACC.w = fmaf(AV.x, g0.w, ACC.w); \
                ACC.x = fmaf(AV.y, g1.x, ACC.x); ACC.y = fmaf(AV.y, g1.y, ACC.y); \
                ACC.z = fmaf(AV.y, g1.z, ACC.z); ACC.w = fmaf(AV.y, g1.w, ACC.w); \
                ACC.x = fmaf(AV.z, g2.x, ACC.x); ACC.y = fmaf(AV.z, g2.y, ACC.y); \
                ACC.z = fmaf(AV.z, g2.z, ACC.z); ACC.w = fmaf(AV.z, g2.w, ACC.w); \
                ACC.x = fmaf(AV.w, g3.x, ACC.x); ACC.y = fmaf(AV.w, g3.y, ACC.y); \
                ACC.z = fmaf(AV.w, g3.z, ACC.z); ACC.w = fmaf(AV.w, g3.w, ACC.w);
                ACC4(acc0, a0) ACC4(acc1, a1) ACC4(acc2, a2) ACC4(acc3, a3)
            }
            int l = lg * 4;
            w2p1[(l + 0) * 9 + rg] = acc0.x * st0.x + acc0.y * st0.y + acc0.z * st0.z + acc0.w * st0.w;
            w2p1[(l + 1) * 9 + rg] = acc1.x * st1.x + acc1.y * st1.y + acc1.z * st1.z + acc1.w * st1.w;
            w2p1[(l + 2) * 9 + rg] = acc2.x * st2.x + acc2.y * st2.y + acc2.z * st2.z + acc2.w * st2.w;
            w2p1[(l + 3) * 9 + rg] = acc3.x * st3.x + acc3.y * st3.y + acc3.z * st3.z + acc3.w * st3.w;
        } else {
            int t2 = task - 90;
            int rg = t2 / 10, lg = t2 - rg * 10;
            const float* Cb = Cm + rg * 4 * 44;
            const float* Hb = Hs + lg * 4;
#pragma unroll
            for (int lp4 = 0; lp4 < 10; lp4++) {
                float4 a0 = *(const float4*)(Cb + lp4 * 4);
                float4 a1 = *(const float4*)(Cb + 44 + lp4 * 4);
                float4 a2 = *(const float4*)(Cb + 88 + lp4 * 4);
                float4 a3 = *(const float4*)(Cb + 132 + lp4 * 4);
                if (lp4 == lg) { st0 = a0; st1 = a1; st2 = a2; st3 = a3; }
                float4 g0 = *(const float4*)(Hb + (lp4 * 4 + 0) * 40);
                float4 g1 = *(const float4*)(Hb + (lp4 * 4 + 1) * 40);
                float4 g2 = *(const float4*)(Hb + (lp4 * 4 + 2) * 40);
                float4 g3 = *(const float4*)(Hb + (lp4 * 4 + 3) * 40);
                ACC4(acc0, a0) ACC4(acc1, a1) ACC4(acc2, a2) ACC4(acc3, a3)
#undef ACC4
            }
            int r = rg * 4;
            w2p2[(r + 0) * 10 + lg] = acc0.x * st0.x + acc0.y * st0.y + acc0.z * st0.z + acc0.w * st0.w;
            w2p2[(r + 1) * 10 + lg] = acc1.x * st1.x + acc1.y * st1.y + acc1.z * st1.z + acc1.w * st1.w;
            w2p2[(r + 2) * 10 + lg] = acc2.x * st2.x + acc2.y * st2.y + acc2.z * st2.z + acc2.w * st2.w;
            w2p2[(r + 3) * 10 + lg] = acc3.x * st3.x + acc3.y * st3.y + acc3.z * st3.z + acc3.w * st3.w;
        }
    }
    __syncthreads();

    if (tid < NL) {
        int l = tid; float w12 = 0.f, w2 = 0.f;
#pragma unroll
        for (int r = 0; r < NR; r++) w12 = fmaf(Am[l * 44 + r], Pb[r], w12);
#pragma unroll
        for (int k = 0; k < 9; k++) w2 += w2p1[l * 9 + k];
        float den = fmaxf(g_w1t[i] * sqrtf(fmaxf(w2, 0.f)), EPSF);
        s1s[l] = __fdividef(w12, den);
    } else if (tid >= 64 && tid < 64 + NR) {
        int r = tid - 64; float w12 = 0.f, w2 = 0.f;
#pragma unroll
        for (int l = 0; l < NL; l++) w12 = fmaf(Cm[r * 44 + l], Qi[l], w12);
#pragma unroll
        for (int k = 0; k < 10; k++) w2 += w2p2[r * 10 + k];
        float den = fmaxf(g_w1i[b] * sqrtf(fmaxf(w2, 0.f)), EPSF);
        s2s[r] = __fdividef(w12, den);
    }
    __syncthreads();

    if (tid == 0) {
        float m1 = 0.f, m2 = 0.f;
#pragma unroll
        for (int l = 0; l < NL; l++) m1 += s1s[l];
#pragma unroll
        for (int r = 0; r < NR; r++) m2 += s2s[r];
        out[(size_t)b * NB + i] = g_base[b * NB + i] + m1 * (1.f / NL) + m2 * (1.f / NR);
    }
}

// ============================ launch ============================
extern "C" void kernel_launch(void* const* d_in, const int* in_sizes, int n_in,
                              void* d_out, int out_size) {
    (void)in_sizes; (void)n_in; (void)out_size;
    const float* pool_img = (const float*)d_in[0];
    const float* img_emb  = (const float*)d_in[1];
    const float* pool_txt = (const float*)d_in[2];
    const float* cap_emb  = (const float*)d_in[3];
    float* out = (float*)d_out;

    cudaFuncSetAttribute((const void*)gram_kernel,
                         cudaFuncAttributeMaxDynamicSharedMemorySize, NL * ND * 4);
    cudaFuncSetAttribute((const void*)s_gemm,
                         cudaFuncAttributeMaxDynamicSharedMemorySize, GEMM_SMEM);
    cudaFuncSetAttribute((const void*)pair_epilogue,
                         cudaFuncAttributeMaxDynamicSharedMemorySize, EPI_SMEM);

    float* dS = nullptr;
    cudaGetSymbolAddress((void**)&dS, g_S);
    __nv_bfloat16* dAh = nullptr; cudaGetSymbolAddress((void**)&dAh, g_Ah);
    __nv_bfloat16* dBh = nullptr; cudaGetSymbolAddress((void**)&dBh, g_Bh);

    // order: s_gemm stays at launch index 3 (profiled slot)
    cvt_kernel<<<9984, 256>>>(img_emb, pool_img, cap_emb, pool_txt);
    gram_kernel<<<NB, 256, NR * ND * 4>>>(img_emb, NR, 0);
    gram_kernel<<<NB, 256, NL * ND * 4>>>(cap_emb, NL, 1);
    s_gemm<<<dim3(41, 74), 256, GEMM_SMEM>>>(dAh, dBh, dS);
    norm_kernel<<<64, 256>>>(pool_img, pool_txt);
    sgemm_tn<<<dim3(NB / 64, NB / 64), 256>>>(pool_img, pool_txt, NB, NB, ND);
    pair_epilogue<<<dim3(NB, NB), 128, EPI_SMEM>>>(dS, out);
}